// round 7
// baseline (speedup 1.0000x reference)
#include <cuda_runtime.h>
#include <math.h>

#define TOK    8192      // B*S
#define DM     1024
#define S_LEN  2048
#define NH     16
#define DK     64
#define QKV_N  3072
#define ST_STRIDE 65

// Scratch (module-static device memory: allowed; no runtime allocation)
__device__ float g_qkv [ (size_t)TOK * QKV_N ];   // [token][3*1024]  (q|k|v, each [h][d])
__device__ float g_attn[ (size_t)TOK * DM    ];   // attention output, [token][h*64+d]

// ---------------------------------------------------------------------------
// Tiled fp32 SGEMM: C[M,N] = A[M,K] @ B[K,N] + bias[N]
// BM=BN=128, BK=8, 256 threads, 8x8 per thread.
// Requires M%128==0, N%128==0, K%8==0 (true for all shapes here).
// ---------------------------------------------------------------------------
__global__ __launch_bounds__(256) void sgemm_bias_kernel(
    const float* __restrict__ A, const float* __restrict__ B,
    const float* __restrict__ bias, float* __restrict__ C,
    int M, int N, int K)
{
    __shared__ float As[8][128];   // transposed A tile: As[k][m]
    __shared__ float Bs[8][128];   // Bs[k][n]

    const int tid = threadIdx.x;
    const int tx  = tid & 15;      // 0..15 (col group)
    const int ty  = tid >> 4;      // 0..15 (row group)

    const int a_row = tid >> 1;          // 0..127
    const int a_col = (tid & 1) << 2;    // 0 or 4
    const int b_row = tid >> 5;          // 0..7
    const int b_col = (tid & 31) << 2;   // 0..124 step 4

    const float* Ab = A + (size_t)(blockIdx.y * 128) * K;
    const float* Bb = B + blockIdx.x * 128;

    float acc[8][8];
    #pragma unroll
    for (int i = 0; i < 8; i++)
        #pragma unroll
        for (int j = 0; j < 8; j++) acc[i][j] = 0.0f;

    for (int k0 = 0; k0 < K; k0 += 8) {
        float4 av = *(const float4*)(Ab + (size_t)a_row * K + k0 + a_col);
        As[a_col + 0][a_row] = av.x;
        As[a_col + 1][a_row] = av.y;
        As[a_col + 2][a_row] = av.z;
        As[a_col + 3][a_row] = av.w;
        *(float4*)(&Bs[b_row][b_col]) =
            *(const float4*)(Bb + (size_t)(k0 + b_row) * N + b_col);
        __syncthreads();

        #pragma unroll
        for (int k = 0; k < 8; k++) {
            float a_frag[8], b_frag[8];
            *(float4*)&a_frag[0] = *(const float4*)&As[k][ty * 8];
            *(float4*)&a_frag[4] = *(const float4*)&As[k][ty * 8 + 4];
            *(float4*)&b_frag[0] = *(const float4*)&Bs[k][tx * 8];
            *(float4*)&b_frag[4] = *(const float4*)&Bs[k][tx * 8 + 4];
            #pragma unroll
            for (int i = 0; i < 8; i++)
                #pragma unroll
                for (int j = 0; j < 8; j++)
                    acc[i][j] += a_frag[i] * b_frag[j];
        }
        __syncthreads();
    }

    const int crow = blockIdx.y * 128 + ty * 8;
    const int ccol = blockIdx.x * 128 + tx * 8;
    #pragma unroll
    for (int i = 0; i < 8; i++) {
        #pragma unroll
        for (int jv = 0; jv < 8; jv += 4) {
            float4 o;
            o.x = acc[i][jv + 0] + bias[ccol + jv + 0];
            o.y = acc[i][jv + 1] + bias[ccol + jv + 1];
            o.z = acc[i][jv + 2] + bias[ccol + jv + 2];
            o.w = acc[i][jv + 3] + bias[ccol + jv + 3];
            *(float4*)(C + (size_t)(crow + i) * N + ccol + jv) = o;
        }
    }
}

// ---------------------------------------------------------------------------
// Flash attention (fp32, online softmax) with relative position bias.
// One block per (q_tile of 64, head, batch). 256 threads, 4x4 micro-tiles.
// Dynamic smem layout (floats):
//   Qt [64][64]  Qt[d][r]        4096
//   Ks [64][64]  Ks[d][c]        4096
//   Vs [64][64]  Vs[c][d]        4096
//   St [64][65]  St[c*65 + r]    4160   (scores/probs, transposed, padded)
//   escale[64], invl[64], bias_s[128]
// ---------------------------------------------------------------------------
#define ATTN_SMEM_FLOATS (4096*3 + 64*ST_STRIDE + 64 + 64 + 128)
#define ATTN_SMEM_BYTES  (ATTN_SMEM_FLOATS * 4)

extern __shared__ float attn_smem[];

__global__ __launch_bounds__(256) void attn_kernel(const float* __restrict__ rel_bias)
{
    float* Qt       = attn_smem;
    float* Ks       = Qt + 4096;
    float* Vs       = Ks + 4096;
    float* St       = Vs + 4096;
    float* escale_s = St + 64 * ST_STRIDE;
    float* invl_s   = escale_s + 64;
    float* bias_s   = invl_s + 64;

    const int tid = threadIdx.x;
    const int tx  = tid & 15;     // col group (keys / dims)
    const int ty  = tid >> 4;     // row group (queries)

    const int q0   = blockIdx.x * 64;       // query base within sequence
    const int h    = blockIdx.y;
    const int b    = blockIdx.z;
    const int t0   = b * S_LEN + q0;        // global token of first query
    const int tb0  = b * S_LEN;
    const int qoff = h * DK;

    // Load Q tile, transposed: Qt[d][r]
    #pragma unroll
    for (int it = 0; it < 4; it++) {
        int flat = tid + it * 256;          // float4 index 0..1023
        int r  = flat >> 4;
        int d0 = (flat & 15) << 2;
        float4 v = *(const float4*)(g_qkv + (size_t)(t0 + r) * QKV_N + qoff + d0);
        Qt[(d0 + 0) * 64 + r] = v.x;
        Qt[(d0 + 1) * 64 + r] = v.y;
        Qt[(d0 + 2) * 64 + r] = v.z;
        Qt[(d0 + 3) * 64 + r] = v.w;
    }

    float o[4][4];
    #pragma unroll
    for (int i = 0; i < 4; i++)
        #pragma unroll
        for (int j = 0; j < 4; j++) o[i][j] = 0.0f;

    float m_r = -1e30f, l_r = 0.0f;   // used by tid<64 only

    for (int j0 = 0; j0 < S_LEN; j0 += 64) {
        __syncthreads();   // previous iteration's reads of Ks/Vs/St complete

        // Load K (transposed) and V tiles
        #pragma unroll
        for (int it = 0; it < 4; it++) {
            int flat = tid + it * 256;
            int c  = flat >> 4;
            int d0 = (flat & 15) << 2;
            const float* base = g_qkv + (size_t)(tb0 + j0 + c) * QKV_N + qoff;
            float4 kv = *(const float4*)(base + 1024 + d0);
            Ks[(d0 + 0) * 64 + c] = kv.x;
            Ks[(d0 + 1) * 64 + c] = kv.y;
            Ks[(d0 + 2) * 64 + c] = kv.z;
            Ks[(d0 + 3) * 64 + c] = kv.w;
            float4 vv = *(const float4*)(base + 2048 + d0);
            *(float4*)&Vs[c * 64 + d0] = vv;
        }
        // Stage the 127 distinct bias diagonals for this (q-tile, k-tile) pair
        if (tid < 127) {
            int rel = (q0 - j0) + (tid - 63) + 1024;
            rel = min(max(rel, 0), 2 * 1024);
            bias_s[tid] = __ldg(rel_bias + rel * NH + h);
        }
        __syncthreads();

        // S = Q @ K^T  (4x4 per thread over the d loop)
        float s[4][4];
        #pragma unroll
        for (int i = 0; i < 4; i++)
            #pragma unroll
            for (int j = 0; j < 4; j++) s[i][j] = 0.0f;
        #pragma unroll 8
        for (int d = 0; d < 64; d++) {
            float4 aq = *(const float4*)&Qt[d * 64 + ty * 4];
            float4 bk = *(const float4*)&Ks[d * 64 + tx * 4];
            s[0][0] += aq.x * bk.x; s[0][1] += aq.x * bk.y; s[0][2] += aq.x * bk.z; s[0][3] += aq.x * bk.w;
            s[1][0] += aq.y * bk.x; s[1][1] += aq.y * bk.y; s[1][2] += aq.y * bk.z; s[1][3] += aq.y * bk.w;
            s[2][0] += aq.z * bk.x; s[2][1] += aq.z * bk.y; s[2][2] += aq.z * bk.z; s[2][3] += aq.z * bk.w;
            s[3][0] += aq.w * bk.x; s[3][1] += aq.w * bk.y; s[3][2] += aq.w * bk.z; s[3][3] += aq.w * bk.w;
        }
        // Scale + bias, store transposed: St[c][r]
        #pragma unroll
        for (int jj = 0; jj < 4; jj++) {
            #pragma unroll
            for (int ii = 0; ii < 4; ii++) {
                int bidx = (ty * 4 + ii) - (tx * 4 + jj) + 63;   // 0..126
                St[(tx * 4 + jj) * ST_STRIDE + ty * 4 + ii] =
                    0.125f * s[ii][jj] + bias_s[bidx];
            }
        }
        __syncthreads();

        // Online softmax: one thread per query row
        if (tid < 64) {
            const int r = tid;
            float tmax = -1e30f;
            #pragma unroll 8
            for (int c = 0; c < 64; c++)
                tmax = fmaxf(tmax, St[c * ST_STRIDE + r]);
            float m_new = fmaxf(m_r, tmax);
            float esc   = __expf(m_r - m_new);
            float rs = 0.0f;
            #pragma unroll 8
            for (int c = 0; c < 64; c++) {
                float p = __expf(St[c * ST_STRIDE + r] - m_new);
                St[c * ST_STRIDE + r] = p;
                rs += p;
            }
            l_r = l_r * esc + rs;
            m_r = m_new;
            escale_s[r] = esc;
        }
        __syncthreads();

        // Rescale O, accumulate P @ V
        float esc_i[4];
        #pragma unroll
        for (int ii = 0; ii < 4; ii++) esc_i[ii] = escale_s[ty * 4 + ii];
        #pragma unroll
        for (int ii = 0; ii < 4; ii++)
            #pragma unroll
            for (int jj = 0; jj < 4; jj++) o[ii][jj] *= esc_i[ii];

        #pragma unroll 8
        for (int c = 0; c < 64; c++) {
            const float* Sc = &St[c * ST_STRIDE + ty * 4];
            float p0 = Sc[0], p1 = Sc[1], p2 = Sc[2], p3 = Sc[3];
            float4 vv = *(const float4*)&Vs[c * 64 + tx * 4];
            o[0][0] += p0 * vv.x; o[0][1] += p0 * vv.y; o[0][2] += p0 * vv.z; o[0][3] += p0 * vv.w;
            o[1][0] += p1 * vv.x; o[1][1] += p1 * vv.y; o[1][2] += p1 * vv.z; o[1][3] += p1 * vv.w;
            o[2][0] += p2 * vv.x; o[2][1] += p2 * vv.y; o[2][2] += p2 * vv.z; o[2][3] += p2 * vv.w;
            o[3][0] += p3 * vv.x; o[3][1] += p3 * vv.y; o[3][2] += p3 * vv.z; o[3][3] += p3 * vv.w;
        }
    }

    __syncthreads();
    if (tid < 64) invl_s[tid] = 1.0f / l_r;
    __syncthreads();

    // Normalize and write: g_attn[token][h*64 + d]
    #pragma unroll
    for (int ii = 0; ii < 4; ii++) {
        float inv = invl_s[ty * 4 + ii];
        float4 ov;
        ov.x = o[ii][0] * inv;
        ov.y = o[ii][1] * inv;
        ov.z = o[ii][2] * inv;
        ov.w = o[ii][3] * inv;
        *(float4*)(g_attn + (size_t)(t0 + ty * 4 + ii) * DM + qoff + tx * 4) = ov;
    }
}

// ---------------------------------------------------------------------------
// Launch
// ---------------------------------------------------------------------------
extern "C" void kernel_launch(void* const* d_in, const int* in_sizes, int n_in,
                              void* d_out, int out_size)
{
    const float* x        = (const float*)d_in[0];  // [8192,1024]
    const float* W_qkv    = (const float*)d_in[1];  // [1024,3072]
    const float* b_qkv    = (const float*)d_in[2];  // [3072]
    const float* W_out    = (const float*)d_in[3];  // [1024,1024]
    const float* b_out    = (const float*)d_in[4];  // [1024]
    const float* rel_bias = (const float*)d_in[5];  // [2049,16]
    float* out = (float*)d_out;                     // [8192,1024]

    float* qkv_ptr = nullptr;
    float* attn_ptr = nullptr;
    cudaGetSymbolAddress((void**)&qkv_ptr,  g_qkv);
    cudaGetSymbolAddress((void**)&attn_ptr, g_attn);

    cudaFuncSetAttribute(attn_kernel,
                         cudaFuncAttributeMaxDynamicSharedMemorySize,
                         ATTN_SMEM_BYTES);

    // 1) QKV projection: [8192,1024] @ [1024,3072] + b
    {
        dim3 grid(QKV_N / 128, TOK / 128);
        sgemm_bias_kernel<<<grid, 256>>>(x, W_qkv, b_qkv, qkv_ptr,
                                         TOK, QKV_N, DM);
    }
    // 2) Attention with relative bias
    {
        dim3 grid(S_LEN / 64, NH, 4);
        attn_kernel<<<grid, 256, ATTN_SMEM_BYTES>>>(rel_bias);
    }
    // 3) Output projection: [8192,1024] @ [1024,1024] + b
    {
        dim3 grid(DM / 128, TOK / 128);
        sgemm_bias_kernel<<<grid, 256>>>(attn_ptr, W_out, b_out, out,
                                         TOK, DM, DM);
    }
}

// round 13
// speedup vs baseline: 1.2831x; 1.2831x over previous
#include <cuda_runtime.h>
#include <cuda_bf16.h>
#include <math.h>
#include <stdint.h>

#define TOK    8192      // B*S
#define DM     1024
#define S_LEN  2048
#define NH     16
#define DK     64
#define QKV_N  3072
#define KP     3072      // K' = 3*1024 (hi/lo split folded into K)
#define ST_STRIDE 65

// ---------------------------------------------------------------------------
// Static device scratch
// ---------------------------------------------------------------------------
__device__ float         g_qkv  [(size_t)TOK   * QKV_N];  // fp32 qkv for attention
__device__ __nv_bfloat16 g_x2   [(size_t)TOK   * KP];     // x split: [hi | lo | hi]
__device__ __nv_bfloat16 g_attn2[(size_t)TOK   * KP];     // attn out split
__device__ __nv_bfloat16 g_w2qkv[(size_t)QKV_N * KP];     // W_qkv^T split: [hi | hi | lo]
__device__ __nv_bfloat16 g_w2out[(size_t)DM    * KP];     // W_out^T split

// ---------------------------------------------------------------------------
// PTX helpers (baseline ISA only: ldmatrix / mma.sync / cp.async — valid on
// plain sm_103 target; NO tcgen05/TMEM which require the 'a' feature set)
// ---------------------------------------------------------------------------
__device__ __forceinline__ uint32_t smem_u32(const void* p) {
    uint32_t a;
    asm("{ .reg .u64 t; cvta.to.shared.u64 t, %1; cvt.u32.u64 %0, t; }"
        : "=r"(a) : "l"(p));
    return a;
}

__device__ __forceinline__ void cp_async16(uint32_t saddr, const void* gaddr) {
    asm volatile("cp.async.cg.shared.global [%0], [%1], 16;"
                 :: "r"(saddr), "l"(gaddr) : "memory");
}

__device__ __forceinline__ void ldmatrix_x4(uint32_t* r, uint32_t addr) {
    asm volatile("ldmatrix.sync.aligned.m8n8.x4.shared.b16 {%0,%1,%2,%3}, [%4];"
                 : "=r"(r[0]), "=r"(r[1]), "=r"(r[2]), "=r"(r[3]) : "r"(addr));
}

__device__ __forceinline__ void mma_bf16(float* c, const uint32_t* a,
                                         uint32_t b0, uint32_t b1) {
    asm volatile(
        "mma.sync.aligned.m16n8k16.row.col.f32.bf16.bf16.f32 "
        "{%0,%1,%2,%3}, {%4,%5,%6,%7}, {%8,%9}, {%0,%1,%2,%3};"
        : "+f"(c[0]), "+f"(c[1]), "+f"(c[2]), "+f"(c[3])
        : "r"(a[0]), "r"(a[1]), "r"(a[2]), "r"(a[3]), "r"(b0), "r"(b1));
}

// ---------------------------------------------------------------------------
// Conversion kernels: fp32 -> bf16 hi/lo split
// x2[row]: [hi(0:1024) | lo(1024:2048) | hi(2048:3072)]
// Wt[n]  : [hi(0:1024) | hi(1024:2048) | lo(2048:3072)]
// => Sum_k' A'[m][k']*B'[n][k'] = hiA*hiB + loA*hiB + hiA*loB
// ---------------------------------------------------------------------------
__global__ __launch_bounds__(256) void convert_x_kernel(
    const float* __restrict__ x, __nv_bfloat16* __restrict__ x2)
{
    size_t i = (size_t)blockIdx.x * 256 + threadIdx.x;
    size_t e = i * 2;
    size_t row = e >> 10;
    int col = (int)(e & 1023);
    float2 v = *(const float2*)(x + row * DM + col);
    __nv_bfloat16 h0 = __float2bfloat16(v.x);
    __nv_bfloat16 h1 = __float2bfloat16(v.y);
    __nv_bfloat16 l0 = __float2bfloat16(v.x - __bfloat162float(h0));
    __nv_bfloat16 l1 = __float2bfloat16(v.y - __bfloat162float(h1));
    __nv_bfloat162 hh = __halves2bfloat162(h0, h1);
    __nv_bfloat162 ll = __halves2bfloat162(l0, l1);
    __nv_bfloat16* base = x2 + row * KP + col;
    *(__nv_bfloat162*)(base)        = hh;
    *(__nv_bfloat162*)(base + 1024) = ll;
    *(__nv_bfloat162*)(base + 2048) = hh;
}

__global__ __launch_bounds__(256) void convert_w_kernel(
    const float* __restrict__ W,       // [1024][N] row-major
    __nv_bfloat16* __restrict__ Wt,    // [N][KP]
    int N)
{
    __shared__ float tile[32][33];
    const int n0 = blockIdx.x * 32, k0 = blockIdx.y * 32;
    const int tx = threadIdx.x, ty = threadIdx.y;
    #pragma unroll
    for (int r = ty; r < 32; r += 8)
        tile[r][tx] = W[(size_t)(k0 + r) * N + n0 + tx];
    __syncthreads();
    #pragma unroll
    for (int r = ty; r < 32; r += 8) {
        int n = n0 + r, k = k0 + tx;
        float f = tile[tx][r];
        __nv_bfloat16 hi = __float2bfloat16(f);
        __nv_bfloat16 lo = __float2bfloat16(f - __bfloat162float(hi));
        __nv_bfloat16* p = Wt + (size_t)n * KP + k;
        p[0]    = hi;
        p[1024] = hi;
        p[2048] = lo;
    }
}

// ---------------------------------------------------------------------------
// HMMA bf16 GEMM: C[M][Nc] = A'[M][KP] @ Bt'[Nc][KP]^T + bias  (fp32 out)
// 128x128 tile, BK=32, 256 threads (8 warps in 4x2), each warp 32x64 via
// m16n8k16. Double-buffered cp.async. Smem rows padded to 40 bf16 (80 B)
// -> ldmatrix phases touch all 32 banks exactly once (conflict-free).
// ---------------------------------------------------------------------------
#define BKC        32
#define NKCHUNK    (KP / BKC)       // 96
#define ROW_PAD    40               // bf16 elements per smem row (80 B)
#define STAGE_B    (128 * ROW_PAD * 2)  // 10240 bytes per stage per matrix

__global__ __launch_bounds__(256) void hmma_gemm_kernel(
    const __nv_bfloat16* __restrict__ A,
    const __nv_bfloat16* __restrict__ Bt,
    const float* __restrict__ bias,
    float* __restrict__ C, int Nc)
{
    __shared__ __nv_bfloat16 As[2][128][ROW_PAD];
    __shared__ __nv_bfloat16 Bs[2][128][ROW_PAD];

    const int tid  = threadIdx.x;
    const int lane = tid & 31, wid = tid >> 5;
    const int warp_m = wid & 3;        // 0..3 -> 32-row slab
    const int warp_n = wid >> 2;       // 0..1 -> 64-col slab
    const int m0 = blockIdx.y * 128, n0 = blockIdx.x * 128;

    const __nv_bfloat16* Ab = A  + (size_t)m0 * KP;
    const __nv_bfloat16* Bb = Bt + (size_t)n0 * KP;

    const uint32_t sbA = smem_u32(&As[0][0][0]);
    const uint32_t sbB = smem_u32(&Bs[0][0][0]);

    // per-thread cp.async slots: 2 chunks of 16B per matrix per stage
    const int c_row0 = tid >> 1;                 // chunks t and t+256
    const int c_c40  = (tid & 1) << 1;           // wait: chunk = tid + i*256
    (void)c_row0; (void)c_c40;

    // ldmatrix per-lane base addresses
    const uint32_t a_base = sbA
        + (uint32_t)((warp_m * 32 + (lane & 15)) * (ROW_PAD * 2))
        + (uint32_t)((lane >> 4) * 16);
    const uint32_t b_base = sbB
        + (uint32_t)((warp_n * 64 + (lane & 7) + ((lane >> 4) & 1) * 8) * (ROW_PAD * 2))
        + (uint32_t)(((lane >> 3) & 1) * 16);

    float acc[2][8][4];
    #pragma unroll
    for (int mt = 0; mt < 2; mt++)
        #pragma unroll
        for (int nt = 0; nt < 8; nt++)
            #pragma unroll
            for (int q = 0; q < 4; q++) acc[mt][nt][q] = 0.0f;

    // ---- stage loader: 512 16B chunks per matrix, 2 per thread ----
    auto load_stage = [&](int stage, int k0) {
        #pragma unroll
        for (int i = 0; i < 2; i++) {
            int chunk = tid + i * 256;
            int row = chunk >> 2;          // 0..127
            int c4  = chunk & 3;           // 16B unit within 64B of BK
            uint32_t dst = (uint32_t)(stage * STAGE_B + row * (ROW_PAD * 2) + c4 * 16);
            cp_async16(sbA + dst, Ab + (size_t)row * KP + k0 + c4 * 8);
            cp_async16(sbB + dst, Bb + (size_t)row * KP + k0 + c4 * 8);
        }
        asm volatile("cp.async.commit_group;" ::: "memory");
    };

    load_stage(0, 0);

    for (int kc = 0; kc < NKCHUNK; kc++) {
        const int cur = kc & 1;
        if (kc + 1 < NKCHUNK) {
            load_stage(cur ^ 1, (kc + 1) * BKC);
            asm volatile("cp.async.wait_group 1;" ::: "memory");
        } else {
            asm volatile("cp.async.wait_group 0;" ::: "memory");
        }
        __syncthreads();

        const uint32_t aoff = a_base + cur * STAGE_B;
        const uint32_t boff = b_base + cur * STAGE_B;
        #pragma unroll
        for (int ks = 0; ks < 2; ks++) {
            uint32_t a0[4], a1[4];
            ldmatrix_x4(a0, aoff + ks * 32);
            ldmatrix_x4(a1, aoff + 16 * (ROW_PAD * 2) + ks * 32);
            uint32_t b[4][4];
            #pragma unroll
            for (int nt2 = 0; nt2 < 4; nt2++)
                ldmatrix_x4(b[nt2], boff + nt2 * 16 * (ROW_PAD * 2) + ks * 32);
            #pragma unroll
            for (int nt = 0; nt < 8; nt++) {
                uint32_t bb0 = b[nt >> 1][(nt & 1) * 2 + 0];
                uint32_t bb1 = b[nt >> 1][(nt & 1) * 2 + 1];
                mma_bf16(acc[0][nt], a0, bb0, bb1);
                mma_bf16(acc[1][nt], a1, bb0, bb1);
            }
        }
        __syncthreads();
    }

    // ---- epilogue: bias + fp32 store ----
    const int gr = m0 + warp_m * 32 + (lane >> 2);
    const int gc = n0 + warp_n * 64 + (lane & 3) * 2;
    #pragma unroll
    for (int mt = 0; mt < 2; mt++) {
        #pragma unroll
        for (int nt = 0; nt < 8; nt++) {
            int col = gc + nt * 8;
            float2 bv = *(const float2*)(bias + col);
            int r0 = gr + mt * 16;
            float2 o0 = { acc[mt][nt][0] + bv.x, acc[mt][nt][1] + bv.y };
            float2 o1 = { acc[mt][nt][2] + bv.x, acc[mt][nt][3] + bv.y };
            *(float2*)(C + (size_t)r0 * Nc + col)       = o0;
            *(float2*)(C + (size_t)(r0 + 8) * Nc + col) = o1;
        }
    }
}

// ---------------------------------------------------------------------------
// Flash attention (fp32, online softmax) with relative position bias.
// Epilogue writes bf16 hi/lo split directly into g_attn2.
// ---------------------------------------------------------------------------
#define ATTN_SMEM_FLOATS (4096*3 + 64*ST_STRIDE + 64 + 64 + 128)
#define ATTN_SMEM_BYTES  (ATTN_SMEM_FLOATS * 4)

extern __shared__ float attn_smem[];

__global__ __launch_bounds__(256) void attn_kernel(
    const float* __restrict__ rel_bias, __nv_bfloat16* __restrict__ attn2)
{
    float* Qt       = attn_smem;
    float* Ks       = Qt + 4096;
    float* Vs       = Ks + 4096;
    float* St       = Vs + 4096;
    float* escale_s = St + 64 * ST_STRIDE;
    float* invl_s   = escale_s + 64;
    float* bias_s   = invl_s + 64;

    const int tid = threadIdx.x;
    const int tx  = tid & 15;
    const int ty  = tid >> 4;

    const int q0   = blockIdx.x * 64;
    const int h    = blockIdx.y;
    const int b    = blockIdx.z;
    const int t0   = b * S_LEN + q0;
    const int tb0  = b * S_LEN;
    const int qoff = h * DK;

    #pragma unroll
    for (int it = 0; it < 4; it++) {
        int flat = tid + it * 256;
        int r  = flat >> 4;
        int d0 = (flat & 15) << 2;
        float4 v = *(const float4*)(g_qkv + (size_t)(t0 + r) * QKV_N + qoff + d0);
        Qt[(d0 + 0) * 64 + r] = v.x;
        Qt[(d0 + 1) * 64 + r] = v.y;
        Qt[(d0 + 2) * 64 + r] = v.z;
        Qt[(d0 + 3) * 64 + r] = v.w;
    }

    float o[4][4];
    #pragma unroll
    for (int i = 0; i < 4; i++)
        #pragma unroll
        for (int j = 0; j < 4; j++) o[i][j] = 0.0f;

    float m_r = -1e30f, l_r = 0.0f;

    for (int j0 = 0; j0 < S_LEN; j0 += 64) {
        __syncthreads();

        #pragma unroll
        for (int it = 0; it < 4; it++) {
            int flat = tid + it * 256;
            int c  = flat >> 4;
            int d0 = (flat & 15) << 2;
            const float* base = g_qkv + (size_t)(tb0 + j0 + c) * QKV_N + qoff;
            float4 kv = *(const float4*)(base + 1024 + d0);
            Ks[(d0 + 0) * 64 + c] = kv.x;
            Ks[(d0 + 1) * 64 + c] = kv.y;
            Ks[(d0 + 2) * 64 + c] = kv.z;
            Ks[(d0 + 3) * 64 + c] = kv.w;
            float4 vv = *(const float4*)(base + 2048 + d0);
            *(float4*)&Vs[c * 64 + d0] = vv;
        }
        if (tid < 127) {
            int rel = (q0 - j0) + (tid - 63) + 1024;
            rel = min(max(rel, 0), 2 * 1024);
            bias_s[tid] = __ldg(rel_bias + rel * NH + h);
        }
        __syncthreads();

        float s[4][4];
        #pragma unroll
        for (int i = 0; i < 4; i++)
            #pragma unroll
            for (int j = 0; j < 4; j++) s[i][j] = 0.0f;
        #pragma unroll 8
        for (int d = 0; d < 64; d++) {
            float4 aq = *(const float4*)&Qt[d * 64 + ty * 4];
            float4 bk = *(const float4*)&Ks[d * 64 + tx * 4];
            s[0][0] += aq.x * bk.x; s[0][1] += aq.x * bk.y; s[0][2] += aq.x * bk.z; s[0][3] += aq.x * bk.w;
            s[1][0] += aq.y * bk.x; s[1][1] += aq.y * bk.y; s[1][2] += aq.y * bk.z; s[1][3] += aq.y * bk.w;
            s[2][0] += aq.z * bk.x; s[2][1] += aq.z * bk.y; s[2][2] += aq.z * bk.z; s[2][3] += aq.z * bk.w;
            s[3][0] += aq.w * bk.x; s[3][1] += aq.w * bk.y; s[3][2] += aq.w * bk.z; s[3][3] += aq.w * bk.w;
        }
        #pragma unroll
        for (int jj = 0; jj < 4; jj++) {
            #pragma unroll
            for (int ii = 0; ii < 4; ii++) {
                int bidx = (ty * 4 + ii) - (tx * 4 + jj) + 63;
                St[(tx * 4 + jj) * ST_STRIDE + ty * 4 + ii] =
                    0.125f * s[ii][jj] + bias_s[bidx];
            }
        }
        __syncthreads();

        if (tid < 64) {
            const int r = tid;
            float tmax = -1e30f;
            #pragma unroll 8
            for (int c = 0; c < 64; c++)
                tmax = fmaxf(tmax, St[c * ST_STRIDE + r]);
            float m_new = fmaxf(m_r, tmax);
            float esc   = __expf(m_r - m_new);
            float rs = 0.0f;
            #pragma unroll 8
            for (int c = 0; c < 64; c++) {
                float p = __expf(St[c * ST_STRIDE + r] - m_new);
                St[c * ST_STRIDE + r] = p;
                rs += p;
            }
            l_r = l_r * esc + rs;
            m_r = m_new;
            escale_s[r] = esc;
        }
        __syncthreads();

        float esc_i[4];
        #pragma unroll
        for (int ii = 0; ii < 4; ii++) esc_i[ii] = escale_s[ty * 4 + ii];
        #pragma unroll
        for (int ii = 0; ii < 4; ii++)
            #pragma unroll
            for (int jj = 0; jj < 4; jj++) o[ii][jj] *= esc_i[ii];

        #pragma unroll 8
        for (int c = 0; c < 64; c++) {
            const float* Sc = &St[c * ST_STRIDE + ty * 4];
            float p0 = Sc[0], p1 = Sc[1], p2 = Sc[2], p3 = Sc[3];
            float4 vv = *(const float4*)&Vs[c * 64 + tx * 4];
            o[0][0] += p0 * vv.x; o[0][1] += p0 * vv.y; o[0][2] += p0 * vv.z; o[0][3] += p0 * vv.w;
            o[1][0] += p1 * vv.x; o[1][1] += p1 * vv.y; o[1][2] += p1 * vv.z; o[1][3] += p1 * vv.w;
            o[2][0] += p2 * vv.x; o[2][1] += p2 * vv.y; o[2][2] += p2 * vv.z; o[2][3] += p2 * vv.w;
            o[3][0] += p3 * vv.x; o[3][1] += p3 * vv.y; o[3][2] += p3 * vv.z; o[3][3] += p3 * vv.w;
        }
    }

    __syncthreads();
    if (tid < 64) invl_s[tid] = 1.0f / l_r;
    __syncthreads();

    #pragma unroll
    for (int ii = 0; ii < 4; ii++) {
        float inv = invl_s[ty * 4 + ii];
        float v0 = o[ii][0] * inv, v1 = o[ii][1] * inv;
        float v2 = o[ii][2] * inv, v3 = o[ii][3] * inv;
        __nv_bfloat16 h0 = __float2bfloat16(v0), h1 = __float2bfloat16(v1);
        __nv_bfloat16 h2 = __float2bfloat16(v2), h3 = __float2bfloat16(v3);
        __nv_bfloat16 l0 = __float2bfloat16(v0 - __bfloat162float(h0));
        __nv_bfloat16 l1 = __float2bfloat16(v1 - __bfloat162float(h1));
        __nv_bfloat16 l2 = __float2bfloat16(v2 - __bfloat162float(h2));
        __nv_bfloat16 l3 = __float2bfloat16(v3 - __bfloat162float(h3));
        __nv_bfloat162 hh01 = __halves2bfloat162(h0, h1);
        __nv_bfloat162 hh23 = __halves2bfloat162(h2, h3);
        __nv_bfloat162 ll01 = __halves2bfloat162(l0, l1);
        __nv_bfloat162 ll23 = __halves2bfloat162(l2, l3);
        __nv_bfloat16* base = attn2 + (size_t)(t0 + ty * 4 + ii) * KP + qoff + tx * 4;
        *(__nv_bfloat162*)(base + 0)    = hh01;
        *(__nv_bfloat162*)(base + 2)    = hh23;
        *(__nv_bfloat162*)(base + 1024) = ll01;
        *(__nv_bfloat162*)(base + 1026) = ll23;
        *(__nv_bfloat162*)(base + 2048) = hh01;
        *(__nv_bfloat162*)(base + 2050) = hh23;
    }
}

// ---------------------------------------------------------------------------
// Launch
// ---------------------------------------------------------------------------
extern "C" void kernel_launch(void* const* d_in, const int* in_sizes, int n_in,
                              void* d_out, int out_size)
{
    const float* x        = (const float*)d_in[0];  // [8192,1024]
    const float* W_qkv    = (const float*)d_in[1];  // [1024,3072]
    const float* b_qkv    = (const float*)d_in[2];  // [3072]
    const float* W_out    = (const float*)d_in[3];  // [1024,1024]
    const float* b_out    = (const float*)d_in[4];  // [1024]
    const float* rel_bias = (const float*)d_in[5];  // [2049,16]
    float* out = (float*)d_out;                     // [8192,1024]

    float* qkv_ptr = nullptr;
    __nv_bfloat16 *x2p = nullptr, *a2p = nullptr, *wqp = nullptr, *wop = nullptr;
    cudaGetSymbolAddress((void**)&qkv_ptr, g_qkv);
    cudaGetSymbolAddress((void**)&x2p,  g_x2);
    cudaGetSymbolAddress((void**)&a2p,  g_attn2);
    cudaGetSymbolAddress((void**)&wqp,  g_w2qkv);
    cudaGetSymbolAddress((void**)&wop,  g_w2out);

    cudaFuncSetAttribute(attn_kernel,
                         cudaFuncAttributeMaxDynamicSharedMemorySize,
                         ATTN_SMEM_BYTES);

    // 0) Conversions (hi/lo bf16 split; W transposed to [N][K'])
    convert_x_kernel<<<TOK * DM / 512, 256>>>(x, x2p);
    {
        dim3 wb(32, 8);
        convert_w_kernel<<<dim3(QKV_N / 32, DM / 32), wb>>>(W_qkv, wqp, QKV_N);
        convert_w_kernel<<<dim3(DM / 32, DM / 32),   wb>>>(W_out, wop, DM);
    }

    // 1) QKV projection (HMMA bf16 split): [8192,3072] fp32
    {
        dim3 grid(QKV_N / 128, TOK / 128);
        hmma_gemm_kernel<<<grid, 256>>>(x2p, wqp, b_qkv, qkv_ptr, QKV_N);
    }
    // 2) Attention with relative bias (fp32), writes split bf16
    {
        dim3 grid(S_LEN / 64, NH, 4);
        attn_kernel<<<grid, 256, ATTN_SMEM_BYTES>>>(rel_bias, a2p);
    }
    // 3) Output projection (HMMA bf16 split): [8192,1024] fp32 -> d_out
    {
        dim3 grid(DM / 128, TOK / 128);
        hmma_gemm_kernel<<<grid, 256>>>(a2p, wop, b_out, out, DM);
    }
}

// round 14
// speedup vs baseline: 2.0076x; 1.5647x over previous
#include <cuda_runtime.h>
#include <cuda_bf16.h>
#include <math.h>
#include <stdint.h>

#define TOK    8192      // B*S
#define DM     1024
#define S_LEN  2048
#define NH     16
#define DK     64
#define QKV_N  3072
#define KP     3072      // K' = 3*1024 (hi/lo split folded into K)
#define ST_STRIDE 65

// ---------------------------------------------------------------------------
// Static device scratch
// ---------------------------------------------------------------------------
__device__ __nv_bfloat16 g_x2   [(size_t)TOK   * KP];   // x split: [hi | lo | hi]
__device__ __nv_bfloat16 g_attn2[(size_t)TOK   * KP];   // attn out split
__device__ __nv_bfloat16 g_w2qkv[(size_t)QKV_N * KP];   // W_qkv^T split: [hi|hi|lo]
__device__ __nv_bfloat16 g_w2out[(size_t)DM    * KP];   // W_out^T split
// attention operands, pre-split, per (b,h) contiguous:
__device__ __nv_bfloat16 g_q2 [(size_t)4 * NH * S_LEN * 192];  // [bh][s][hi|lo|hi d]
__device__ __nv_bfloat16 g_k2 [(size_t)4 * NH * S_LEN * 192];  // [bh][s][hi|hi|lo d]
__device__ __nv_bfloat16 g_vhi[(size_t)4 * NH * S_LEN * 64];
__device__ __nv_bfloat16 g_vlo[(size_t)4 * NH * S_LEN * 64];

// ---------------------------------------------------------------------------
// PTX helpers (baseline ISA: ldmatrix / mma.sync / cp.async — valid on sm_103)
// ---------------------------------------------------------------------------
__device__ __forceinline__ uint32_t smem_u32(const void* p) {
    uint32_t a;
    asm("{ .reg .u64 t; cvta.to.shared.u64 t, %1; cvt.u32.u64 %0, t; }"
        : "=r"(a) : "l"(p));
    return a;
}

__device__ __forceinline__ void cp_async16(uint32_t saddr, const void* gaddr) {
    asm volatile("cp.async.cg.shared.global [%0], [%1], 16;"
                 :: "r"(saddr), "l"(gaddr) : "memory");
}

__device__ __forceinline__ void ldmatrix_x4(uint32_t* r, uint32_t addr) {
    asm volatile("ldmatrix.sync.aligned.m8n8.x4.shared.b16 {%0,%1,%2,%3}, [%4];"
                 : "=r"(r[0]), "=r"(r[1]), "=r"(r[2]), "=r"(r[3]) : "r"(addr));
}

__device__ __forceinline__ void ldmatrix_x4_trans(uint32_t* r, uint32_t addr) {
    asm volatile("ldmatrix.sync.aligned.m8n8.x4.trans.shared.b16 {%0,%1,%2,%3}, [%4];"
                 : "=r"(r[0]), "=r"(r[1]), "=r"(r[2]), "=r"(r[3]) : "r"(addr));
}

__device__ __forceinline__ void mma_bf16(float* c, const uint32_t* a,
                                         uint32_t b0, uint32_t b1) {
    asm volatile(
        "mma.sync.aligned.m16n8k16.row.col.f32.bf16.bf16.f32 "
        "{%0,%1,%2,%3}, {%4,%5,%6,%7}, {%8,%9}, {%0,%1,%2,%3};"
        : "+f"(c[0]), "+f"(c[1]), "+f"(c[2]), "+f"(c[3])
        : "r"(a[0]), "r"(a[1]), "r"(a[2]), "r"(a[3]), "r"(b0), "r"(b1));
}

__device__ __forceinline__ void split2(float x, float y,
                                       __nv_bfloat162& hh, __nv_bfloat162& ll) {
    __nv_bfloat16 h0 = __float2bfloat16(x);
    __nv_bfloat16 h1 = __float2bfloat16(y);
    __nv_bfloat16 l0 = __float2bfloat16(x - __bfloat162float(h0));
    __nv_bfloat16 l1 = __float2bfloat16(y - __bfloat162float(h1));
    hh = __halves2bfloat162(h0, h1);
    ll = __halves2bfloat162(l0, l1);
}

// ---------------------------------------------------------------------------
// Conversion kernels
// ---------------------------------------------------------------------------
__global__ __launch_bounds__(256) void convert_x_kernel(
    const float* __restrict__ x, __nv_bfloat16* __restrict__ x2)
{
    size_t i = (size_t)blockIdx.x * 256 + threadIdx.x;
    size_t e = i * 2;
    size_t row = e >> 10;
    int col = (int)(e & 1023);
    float2 v = *(const float2*)(x + row * DM + col);
    __nv_bfloat162 hh, ll;
    split2(v.x, v.y, hh, ll);
    __nv_bfloat16* base = x2 + row * KP + col;
    *(__nv_bfloat162*)(base)        = hh;
    *(__nv_bfloat162*)(base + 1024) = ll;
    *(__nv_bfloat162*)(base + 2048) = hh;
}

__global__ __launch_bounds__(256) void convert_w_kernel(
    const float* __restrict__ W,       // [1024][N] row-major
    __nv_bfloat16* __restrict__ Wt,    // [N][KP]
    int N)
{
    __shared__ float tile[32][33];
    const int n0 = blockIdx.x * 32, k0 = blockIdx.y * 32;
    const int tx = threadIdx.x, ty = threadIdx.y;
    #pragma unroll
    for (int r = ty; r < 32; r += 8)
        tile[r][tx] = W[(size_t)(k0 + r) * N + n0 + tx];
    __syncthreads();
    #pragma unroll
    for (int r = ty; r < 32; r += 8) {
        int n = n0 + r, k = k0 + tx;
        float f = tile[tx][r];
        __nv_bfloat16 hi = __float2bfloat16(f);
        __nv_bfloat16 lo = __float2bfloat16(f - __bfloat162float(hi));
        __nv_bfloat16* p = Wt + (size_t)n * KP + k;
        p[0]    = hi;
        p[1024] = hi;
        p[2048] = lo;
    }
}

// ---------------------------------------------------------------------------
// HMMA GEMM mainloop (shared by both epilogues)
// 128x128 tile, BK=32, 256 threads (8 warps 4x2), m16n8k16, 2-stage cp.async
// ---------------------------------------------------------------------------
#define BKC        32
#define NKCHUNK    (KP / BKC)           // 96
#define ROW_PAD    40
#define STAGE_B    (128 * ROW_PAD * 2)

struct GemmCtx {
    float acc[2][8][4];
    int gr, gc;   // first output row/col of this thread
};

__device__ __forceinline__ void hmma_mainloop(
    const __nv_bfloat16* __restrict__ A,
    const __nv_bfloat16* __restrict__ Bt,
    __nv_bfloat16 (*As)[128][ROW_PAD], __nv_bfloat16 (*Bs)[128][ROW_PAD],
    GemmCtx& ctx)
{
    const int tid  = threadIdx.x;
    const int lane = tid & 31, wid = tid >> 5;
    const int warp_m = wid & 3;
    const int warp_n = wid >> 2;
    const int m0 = blockIdx.y * 128, n0 = blockIdx.x * 128;

    const __nv_bfloat16* Ab = A  + (size_t)m0 * KP;
    const __nv_bfloat16* Bb = Bt + (size_t)n0 * KP;

    const uint32_t sbA = smem_u32(&As[0][0][0]);
    const uint32_t sbB = smem_u32(&Bs[0][0][0]);

    const uint32_t a_base = sbA
        + (uint32_t)((warp_m * 32 + (lane & 15)) * (ROW_PAD * 2))
        + (uint32_t)((lane >> 4) * 16);
    const uint32_t b_base = sbB
        + (uint32_t)((warp_n * 64 + (lane & 7) + ((lane >> 4) & 1) * 8) * (ROW_PAD * 2))
        + (uint32_t)(((lane >> 3) & 1) * 16);

    #pragma unroll
    for (int mt = 0; mt < 2; mt++)
        #pragma unroll
        for (int nt = 0; nt < 8; nt++)
            #pragma unroll
            for (int q = 0; q < 4; q++) ctx.acc[mt][nt][q] = 0.0f;

    auto load_stage = [&](int stage, int k0) {
        #pragma unroll
        for (int i = 0; i < 2; i++) {
            int chunk = tid + i * 256;
            int row = chunk >> 2;
            int c4  = chunk & 3;
            uint32_t dst = (uint32_t)(stage * STAGE_B + row * (ROW_PAD * 2) + c4 * 16);
            cp_async16(sbA + dst, Ab + (size_t)row * KP + k0 + c4 * 8);
            cp_async16(sbB + dst, Bb + (size_t)row * KP + k0 + c4 * 8);
        }
        asm volatile("cp.async.commit_group;" ::: "memory");
    };

    load_stage(0, 0);

    for (int kc = 0; kc < NKCHUNK; kc++) {
        const int cur = kc & 1;
        if (kc + 1 < NKCHUNK) {
            load_stage(cur ^ 1, (kc + 1) * BKC);
            asm volatile("cp.async.wait_group 1;" ::: "memory");
        } else {
            asm volatile("cp.async.wait_group 0;" ::: "memory");
        }
        __syncthreads();

        const uint32_t aoff = a_base + cur * STAGE_B;
        const uint32_t boff = b_base + cur * STAGE_B;
        #pragma unroll
        for (int ks = 0; ks < 2; ks++) {
            uint32_t a0[4], a1[4];
            ldmatrix_x4(a0, aoff + ks * 32);
            ldmatrix_x4(a1, aoff + 16 * (ROW_PAD * 2) + ks * 32);
            uint32_t b[4][4];
            #pragma unroll
            for (int nt2 = 0; nt2 < 4; nt2++)
                ldmatrix_x4(b[nt2], boff + nt2 * 16 * (ROW_PAD * 2) + ks * 32);
            #pragma unroll
            for (int nt = 0; nt < 8; nt++) {
                uint32_t bb0 = b[nt >> 1][(nt & 1) * 2 + 0];
                uint32_t bb1 = b[nt >> 1][(nt & 1) * 2 + 1];
                mma_bf16(ctx.acc[0][nt], a0, bb0, bb1);
                mma_bf16(ctx.acc[1][nt], a1, bb0, bb1);
            }
        }
        __syncthreads();
    }

    ctx.gr = m0 + warp_m * 32 + (lane >> 2);
    ctx.gc = n0 + warp_n * 64 + (lane & 3) * 2;
}

// Generic fp32 output (used for out-projection -> d_out)
__global__ __launch_bounds__(256) void hmma_gemm_kernel(
    const __nv_bfloat16* __restrict__ A,
    const __nv_bfloat16* __restrict__ Bt,
    const float* __restrict__ bias,
    float* __restrict__ C, int Nc)
{
    __shared__ __nv_bfloat16 As[2][128][ROW_PAD];
    __shared__ __nv_bfloat16 Bs[2][128][ROW_PAD];
    GemmCtx ctx;
    hmma_mainloop(A, Bt, As, Bs, ctx);

    #pragma unroll
    for (int mt = 0; mt < 2; mt++) {
        #pragma unroll
        for (int nt = 0; nt < 8; nt++) {
            int col = ctx.gc + nt * 8;
            float2 bv = *(const float2*)(bias + col);
            int r0 = ctx.gr + mt * 16;
            float2 o0 = { ctx.acc[mt][nt][0] + bv.x, ctx.acc[mt][nt][1] + bv.y };
            float2 o1 = { ctx.acc[mt][nt][2] + bv.x, ctx.acc[mt][nt][3] + bv.y };
            *(float2*)(C + (size_t)r0 * Nc + col)       = o0;
            *(float2*)(C + (size_t)(r0 + 8) * Nc + col) = o1;
        }
    }
}

// QKV variant: writes pre-split attention operands q2/k2/vhi/vlo
__global__ __launch_bounds__(256) void hmma_gemm_qkv_kernel(
    const __nv_bfloat16* __restrict__ A,
    const __nv_bfloat16* __restrict__ Bt,
    const float* __restrict__ bias,
    __nv_bfloat16* __restrict__ q2, __nv_bfloat16* __restrict__ k2,
    __nv_bfloat16* __restrict__ vhi, __nv_bfloat16* __restrict__ vlo)
{
    __shared__ __nv_bfloat16 As[2][128][ROW_PAD];
    __shared__ __nv_bfloat16 Bs[2][128][ROW_PAD];
    GemmCtx ctx;
    hmma_mainloop(A, Bt, As, Bs, ctx);

    #pragma unroll
    for (int mt = 0; mt < 2; mt++) {
        #pragma unroll
        for (int rr = 0; rr < 2; rr++) {
            int r  = ctx.gr + mt * 16 + rr * 8;     // token
            int bb = r >> 11, ss = r & 2047;
            #pragma unroll
            for (int nt = 0; nt < 8; nt++) {
                int col = ctx.gc + nt * 8;
                float2 bv = *(const float2*)(bias + col);
                float x = ctx.acc[mt][nt][rr * 2 + 0] + bv.x;
                float y = ctx.acc[mt][nt][rr * 2 + 1] + bv.y;
                __nv_bfloat162 hh, ll;
                split2(x, y, hh, ll);
                int sec = col >> 10;
                int h = (col & 1023) >> 6, d = col & 63;
                if (sec < 2) {
                    size_t base = ((size_t)(bb * NH + h) * S_LEN + ss) * 192 + d;
                    if (sec == 0) {            // Q: [hi | lo | hi]
                        *(__nv_bfloat162*)(q2 + base)       = hh;
                        *(__nv_bfloat162*)(q2 + base + 64)  = ll;
                        *(__nv_bfloat162*)(q2 + base + 128) = hh;
                    } else {                   // K: [hi | hi | lo]
                        *(__nv_bfloat162*)(k2 + base)       = hh;
                        *(__nv_bfloat162*)(k2 + base + 64)  = hh;
                        *(__nv_bfloat162*)(k2 + base + 128) = ll;
                    }
                } else {                       // V planes
                    size_t vb = ((size_t)(bb * NH + h) * S_LEN + ss) * 64 + d;
                    *(__nv_bfloat162*)(vhi + vb) = hh;
                    *(__nv_bfloat162*)(vlo + vb) = ll;
                }
            }
        }
    }
}

// ---------------------------------------------------------------------------
// HMMA flash attention. CTA = (64 queries, head, batch), 128 threads (4 warps,
// 16 q-rows each). K'=192 folded splits for both QK^T and PV. fp32 softmax.
// Smem: Qp[64][200] | Kp/Ps[64][200] (aliased) | Vp[192][72] | St[64][65]f32
// ---------------------------------------------------------------------------
#define QSTR 200
#define VSTR 72
#define OFF_QP 0
#define OFF_KP (64 * QSTR * 2)                    // 25600
#define OFF_VP (OFF_KP + 64 * QSTR * 2)           // 51200
#define OFF_ST (OFF_VP + 192 * VSTR * 2)          // 78848
#define OFF_ES (OFF_ST + 64 * ST_STRIDE * 4)      // 95488
#define OFF_IL (OFF_ES + 256)                     // 95744
#define OFF_BI (OFF_IL + 256)                     // 96000
#define ATTN2_SMEM_BYTES (OFF_BI + 512)           // 96512

__global__ __launch_bounds__(128) void attn_mma_kernel(
    const float* __restrict__ rel_bias, __nv_bfloat16* __restrict__ attn2)
{
    extern __shared__ char smraw[];
    __nv_bfloat16* Ps = (__nv_bfloat16*)(smraw + OFF_KP);
    float* St       = (float*)(smraw + OFF_ST);
    float* escale_s = (float*)(smraw + OFF_ES);
    float* invl_s   = (float*)(smraw + OFF_IL);
    float* bias_s   = (float*)(smraw + OFF_BI);

    const uint32_t sQ = smem_u32(smraw + OFF_QP);
    const uint32_t sK = smem_u32(smraw + OFF_KP);
    const uint32_t sV = smem_u32(smraw + OFF_VP);

    const int tid  = threadIdx.x;
    const int lane = tid & 31, w = tid >> 5;

    const int q0 = blockIdx.x * 64;
    const int h  = blockIdx.y;
    const int b  = blockIdx.z;
    const int bh = b * NH + h;
    const int t0 = b * S_LEN + q0;

    const __nv_bfloat16* qg = g_q2  + ((size_t)bh * S_LEN + q0) * 192;
    const __nv_bfloat16* kg = g_k2  + (size_t)bh * S_LEN * 192;
    const __nv_bfloat16* vh = g_vhi + (size_t)bh * S_LEN * 64;
    const __nv_bfloat16* vl = g_vlo + (size_t)bh * S_LEN * 64;

    // Load Q' tile once (64 rows x 192 -> stride 200)
    for (int c = tid; c < 1536; c += 128) {
        int row = c / 24, u = c % 24;
        cp_async16(sQ + (uint32_t)(row * QSTR * 2 + u * 16),
                   qg + (size_t)row * 192 + u * 8);
    }

    // ldmatrix base addresses
    const uint32_t aQ = sQ + (uint32_t)(((w * 16 + (lane & 15)) * QSTR) * 2
                                        + (lane >> 4) * 16);
    const uint32_t bK = sK + (uint32_t)((((lane & 7) + ((lane >> 4) & 1) * 8) * QSTR) * 2
                                        + ((lane >> 3) & 1) * 16);
    const uint32_t aP = sK + (uint32_t)(((w * 16 + (lane & 15)) * QSTR) * 2
                                        + (lane >> 4) * 16);
    const uint32_t bV = sV + (uint32_t)(((lane & 15) * VSTR) * 2
                                        + (lane >> 4) * 16);

    float o[8][4];
    #pragma unroll
    for (int nt = 0; nt < 8; nt++)
        #pragma unroll
        for (int q = 0; q < 4; q++) o[nt][q] = 0.0f;

    float m_r = -1e30f, l_r = 0.0f;   // valid in tid<64 only

    const int r0 = lane >> 2;          // fragment row within m16
    const int c0 = (lane & 3) * 2;     // fragment col pair

    for (int j0 = 0; j0 < S_LEN; j0 += 64) {
        __syncthreads();   // prev PV reads of Ps/Vp + conversions done

        // --- load K' tile and V' (hi,hi,lo) tile ---
        for (int c = tid; c < 1536; c += 128) {
            int row = c / 24, u = c % 24;
            cp_async16(sK + (uint32_t)(row * QSTR * 2 + u * 16),
                       kg + ((size_t)(j0 + row)) * 192 + u * 8);
        }
        for (int c = tid; c < 512; c += 128) {
            int row = c >> 3, u = c & 7;
            const __nv_bfloat16* sh = vh + (size_t)(j0 + row) * 64 + u * 8;
            const __nv_bfloat16* sl = vl + (size_t)(j0 + row) * 64 + u * 8;
            cp_async16(sV + (uint32_t)(row * VSTR * 2 + u * 16), sh);
            cp_async16(sV + (uint32_t)((row + 64) * VSTR * 2 + u * 16), sh);
            cp_async16(sV + (uint32_t)((row + 128) * VSTR * 2 + u * 16), sl);
        }
        if (tid < 127) {
            int rel = (q0 - j0) + (tid - 63) + 1024;
            rel = min(max(rel, 0), 2 * 1024);
            bias_s[tid] = __ldg(rel_bias + rel * NH + h);
        }
        asm volatile("cp.async.commit_group;" ::: "memory");
        asm volatile("cp.async.wait_group 0;" ::: "memory");
        __syncthreads();

        // --- S = Q' @ K'^T over k'=192 ---
        float sf[8][4];
        #pragma unroll
        for (int nt = 0; nt < 8; nt++)
            #pragma unroll
            for (int q = 0; q < 4; q++) sf[nt][q] = 0.0f;
        #pragma unroll
        for (int kt = 0; kt < 12; kt++) {
            uint32_t a[4];
            ldmatrix_x4(a, aQ + kt * 32);
            #pragma unroll
            for (int np = 0; np < 4; np++) {
                uint32_t bf[4];
                ldmatrix_x4(bf, bK + np * 16 * (QSTR * 2) + kt * 32);
                mma_bf16(sf[np * 2 + 0], a, bf[0], bf[1]);
                mma_bf16(sf[np * 2 + 1], a, bf[2], bf[3]);
            }
        }
        // spill to St (transposed) with scale + relative bias
        {
            const int rA = w * 16 + r0, rB = rA + 8;
            #pragma unroll
            for (int nt = 0; nt < 8; nt++) {
                int c = nt * 8 + c0;
                St[(c) * ST_STRIDE + rA]     = 0.125f * sf[nt][0] + bias_s[rA - c + 63];
                St[(c + 1) * ST_STRIDE + rA] = 0.125f * sf[nt][1] + bias_s[rA - c + 62];
                St[(c) * ST_STRIDE + rB]     = 0.125f * sf[nt][2] + bias_s[rB - c + 63];
                St[(c + 1) * ST_STRIDE + rB] = 0.125f * sf[nt][3] + bias_s[rB - c + 62];
            }
        }
        __syncthreads();

        // --- online softmax (fp32, one thread per query row) ---
        if (tid < 64) {
            const int r = tid;
            float tmax = -1e30f;
            #pragma unroll 8
            for (int c = 0; c < 64; c++)
                tmax = fmaxf(tmax, St[c * ST_STRIDE + r]);
            float m_new = fmaxf(m_r, tmax);
            float esc   = __expf(m_r - m_new);
            float rs = 0.0f;
            #pragma unroll 8
            for (int c = 0; c < 64; c++) {
                float p = __expf(St[c * ST_STRIDE + r] - m_new);
                St[c * ST_STRIDE + r] = p;
                rs += p;
            }
            l_r = l_r * esc + rs;
            m_r = m_new;
            escale_s[r] = esc;
        }
        __syncthreads();

        // --- convert P -> bf16 split into Ps (aliases K tile) ---
        {
            const int r  = tid & 63;
            const int cb = (tid >> 6) * 32;
            __nv_bfloat16* Pr = Ps + r * QSTR;
            #pragma unroll
            for (int c = cb; c < cb + 32; c += 2) {
                float p0 = St[c * ST_STRIDE + r];
                float p1 = St[(c + 1) * ST_STRIDE + r];
                __nv_bfloat162 hh, ll;
                split2(p0, p1, hh, ll);
                *(__nv_bfloat162*)(Pr + c)       = hh;
                *(__nv_bfloat162*)(Pr + 64 + c)  = ll;
                *(__nv_bfloat162*)(Pr + 128 + c) = hh;
            }
        }
        __syncthreads();

        // --- O = O*esc + P' @ V' ---
        {
            float e0 = escale_s[w * 16 + r0];
            float e1 = escale_s[w * 16 + r0 + 8];
            #pragma unroll
            for (int nt = 0; nt < 8; nt++) {
                o[nt][0] *= e0; o[nt][1] *= e0;
                o[nt][2] *= e1; o[nt][3] *= e1;
            }
        }
        #pragma unroll
        for (int kt = 0; kt < 12; kt++) {
            uint32_t a[4];
            ldmatrix_x4(a, aP + kt * 32);
            #pragma unroll
            for (int np = 0; np < 4; np++) {
                uint32_t bf[4];
                ldmatrix_x4_trans(bf, bV + kt * 16 * (VSTR * 2) + np * 32);
                mma_bf16(o[np * 2 + 0], a, bf[0], bf[1]);
                mma_bf16(o[np * 2 + 1], a, bf[2], bf[3]);
            }
        }
    }

    __syncthreads();
    if (tid < 64) invl_s[tid] = 1.0f / l_r;
    __syncthreads();

    // --- epilogue: normalize, split, write g_attn2[token][hi|lo|hi] ---
    {
        const float i0 = invl_s[w * 16 + r0];
        const float i1 = invl_s[w * 16 + r0 + 8];
        const int tok0 = t0 + w * 16 + r0;
        const int colb = h * DK + c0;
        #pragma unroll
        for (int nt = 0; nt < 8; nt++) {
            int col = colb + nt * 8;
            {
                float x = o[nt][0] * i0, y = o[nt][1] * i0;
                __nv_bfloat162 hh, ll;
                split2(x, y, hh, ll);
                __nv_bfloat16* p = attn2 + (size_t)tok0 * KP + col;
                *(__nv_bfloat162*)(p)        = hh;
                *(__nv_bfloat162*)(p + 1024) = ll;
                *(__nv_bfloat162*)(p + 2048) = hh;
            }
            {
                float x = o[nt][2] * i1, y = o[nt][3] * i1;
                __nv_bfloat162 hh, ll;
                split2(x, y, hh, ll);
                __nv_bfloat16* p = attn2 + (size_t)(tok0 + 8) * KP + col;
                *(__nv_bfloat162*)(p)        = hh;
                *(__nv_bfloat162*)(p + 1024) = ll;
                *(__nv_bfloat162*)(p + 2048) = hh;
            }
        }
    }
}

// ---------------------------------------------------------------------------
// Launch
// ---------------------------------------------------------------------------
extern "C" void kernel_launch(void* const* d_in, const int* in_sizes, int n_in,
                              void* d_out, int out_size)
{
    const float* x        = (const float*)d_in[0];
    const float* W_qkv    = (const float*)d_in[1];
    const float* b_qkv    = (const float*)d_in[2];
    const float* W_out    = (const float*)d_in[3];
    const float* b_out    = (const float*)d_in[4];
    const float* rel_bias = (const float*)d_in[5];
    float* out = (float*)d_out;

    __nv_bfloat16 *x2p, *a2p, *wqp, *wop, *q2p, *k2p, *vhp, *vlp;
    cudaGetSymbolAddress((void**)&x2p, g_x2);
    cudaGetSymbolAddress((void**)&a2p, g_attn2);
    cudaGetSymbolAddress((void**)&wqp, g_w2qkv);
    cudaGetSymbolAddress((void**)&wop, g_w2out);
    cudaGetSymbolAddress((void**)&q2p, g_q2);
    cudaGetSymbolAddress((void**)&k2p, g_k2);
    cudaGetSymbolAddress((void**)&vhp, g_vhi);
    cudaGetSymbolAddress((void**)&vlp, g_vlo);

    cudaFuncSetAttribute(attn_mma_kernel,
                         cudaFuncAttributeMaxDynamicSharedMemorySize,
                         ATTN2_SMEM_BYTES);

    // 0) Conversions
    convert_x_kernel<<<TOK * DM / 512, 256>>>(x, x2p);
    {
        dim3 wb(32, 8);
        convert_w_kernel<<<dim3(QKV_N / 32, DM / 32), wb>>>(W_qkv, wqp, QKV_N);
        convert_w_kernel<<<dim3(DM / 32, DM / 32),   wb>>>(W_out, wop, DM);
    }

    // 1) QKV projection -> pre-split attention operands
    {
        dim3 grid(QKV_N / 128, TOK / 128);
        hmma_gemm_qkv_kernel<<<grid, 256>>>(x2p, wqp, b_qkv,
                                            q2p, k2p, vhp, vlp);
    }
    // 2) Attention (HMMA, fp32 softmax), writes split bf16
    {
        dim3 grid(S_LEN / 64, NH, 4);
        attn_mma_kernel<<<grid, 128, ATTN2_SMEM_BYTES>>>(rel_bias, a2p);
    }
    // 3) Output projection -> d_out
    {
        dim3 grid(DM / 128, TOK / 128);
        hmma_gemm_kernel<<<grid, 256>>>(a2p, wop, b_out, out, DM);
    }
}

// round 15
// speedup vs baseline: 2.7862x; 1.3878x over previous
#include <cuda_runtime.h>
#include <cuda_bf16.h>
#include <math.h>
#include <stdint.h>

#define TOK    8192      // B*S
#define DM     1024
#define S_LEN  2048
#define NH     16
#define DK     64
#define QKV_N  3072
#define KP     3072      // K' = 3*1024 (hi/lo split folded into K)

// ---------------------------------------------------------------------------
// Static device scratch
// ---------------------------------------------------------------------------
__device__ __nv_bfloat16 g_x2   [(size_t)TOK   * KP];   // x split: [hi | lo | hi]
__device__ __nv_bfloat16 g_attn2[(size_t)TOK   * KP];   // attn out split
__device__ __nv_bfloat16 g_w2qkv[(size_t)QKV_N * KP];   // W_qkv^T split: [hi|hi|lo]
__device__ __nv_bfloat16 g_w2out[(size_t)DM    * KP];   // W_out^T split
// attention operands, pre-split, per (b,h) contiguous:
__device__ __nv_bfloat16 g_q2 [(size_t)4 * NH * S_LEN * 192];  // [bh][s][hi|lo|hi d]
__device__ __nv_bfloat16 g_k2 [(size_t)4 * NH * S_LEN * 192];  // [bh][s][hi|hi|lo d]
__device__ __nv_bfloat16 g_vhi[(size_t)4 * NH * S_LEN * 64];
__device__ __nv_bfloat16 g_vlo[(size_t)4 * NH * S_LEN * 64];

// ---------------------------------------------------------------------------
// PTX helpers (baseline ISA: ldmatrix / mma.sync / cp.async — valid on sm_103)
// ---------------------------------------------------------------------------
__device__ __forceinline__ uint32_t smem_u32(const void* p) {
    uint32_t a;
    asm("{ .reg .u64 t; cvta.to.shared.u64 t, %1; cvt.u32.u64 %0, t; }"
        : "=r"(a) : "l"(p));
    return a;
}

__device__ __forceinline__ void cp_async16(uint32_t saddr, const void* gaddr) {
    asm volatile("cp.async.cg.shared.global [%0], [%1], 16;"
                 :: "r"(saddr), "l"(gaddr) : "memory");
}

__device__ __forceinline__ void ldmatrix_x4(uint32_t* r, uint32_t addr) {
    asm volatile("ldmatrix.sync.aligned.m8n8.x4.shared.b16 {%0,%1,%2,%3}, [%4];"
                 : "=r"(r[0]), "=r"(r[1]), "=r"(r[2]), "=r"(r[3]) : "r"(addr));
}

__device__ __forceinline__ void ldmatrix_x4_trans(uint32_t* r, uint32_t addr) {
    asm volatile("ldmatrix.sync.aligned.m8n8.x4.trans.shared.b16 {%0,%1,%2,%3}, [%4];"
                 : "=r"(r[0]), "=r"(r[1]), "=r"(r[2]), "=r"(r[3]) : "r"(addr));
}

__device__ __forceinline__ void mma_bf16(float* c, const uint32_t* a,
                                         uint32_t b0, uint32_t b1) {
    asm volatile(
        "mma.sync.aligned.m16n8k16.row.col.f32.bf16.bf16.f32 "
        "{%0,%1,%2,%3}, {%4,%5,%6,%7}, {%8,%9}, {%0,%1,%2,%3};"
        : "+f"(c[0]), "+f"(c[1]), "+f"(c[2]), "+f"(c[3])
        : "r"(a[0]), "r"(a[1]), "r"(a[2]), "r"(a[3]), "r"(b0), "r"(b1));
}

__device__ __forceinline__ void split2(float x, float y,
                                       __nv_bfloat162& hh, __nv_bfloat162& ll) {
    __nv_bfloat16 h0 = __float2bfloat16(x);
    __nv_bfloat16 h1 = __float2bfloat16(y);
    __nv_bfloat16 l0 = __float2bfloat16(x - __bfloat162float(h0));
    __nv_bfloat16 l1 = __float2bfloat16(y - __bfloat162float(h1));
    hh = __halves2bfloat162(h0, h1);
    ll = __halves2bfloat162(l0, l1);
}

__device__ __forceinline__ void pack_hilo(float x, float y,
                                          uint32_t& hh, uint32_t& ll) {
    __nv_bfloat162 h2, l2;
    split2(x, y, h2, l2);
    hh = *reinterpret_cast<uint32_t*>(&h2);
    ll = *reinterpret_cast<uint32_t*>(&l2);
}

// ---------------------------------------------------------------------------
// Conversion kernels
// ---------------------------------------------------------------------------
__global__ __launch_bounds__(256) void convert_x_kernel(
    const float* __restrict__ x, __nv_bfloat16* __restrict__ x2)
{
    size_t i = (size_t)blockIdx.x * 256 + threadIdx.x;
    size_t e = i * 2;
    size_t row = e >> 10;
    int col = (int)(e & 1023);
    float2 v = *(const float2*)(x + row * DM + col);
    __nv_bfloat162 hh, ll;
    split2(v.x, v.y, hh, ll);
    __nv_bfloat16* base = x2 + row * KP + col;
    *(__nv_bfloat162*)(base)        = hh;
    *(__nv_bfloat162*)(base + 1024) = ll;
    *(__nv_bfloat162*)(base + 2048) = hh;
}

__global__ __launch_bounds__(256) void convert_w_kernel(
    const float* __restrict__ W,       // [1024][N] row-major
    __nv_bfloat16* __restrict__ Wt,    // [N][KP]
    int N)
{
    __shared__ float tile[32][33];
    const int n0 = blockIdx.x * 32, k0 = blockIdx.y * 32;
    const int tx = threadIdx.x, ty = threadIdx.y;
    #pragma unroll
    for (int r = ty; r < 32; r += 8)
        tile[r][tx] = W[(size_t)(k0 + r) * N + n0 + tx];
    __syncthreads();
    #pragma unroll
    for (int r = ty; r < 32; r += 8) {
        int n = n0 + r, k = k0 + tx;
        float f = tile[tx][r];
        __nv_bfloat16 hi = __float2bfloat16(f);
        __nv_bfloat16 lo = __float2bfloat16(f - __bfloat162float(hi));
        __nv_bfloat16* p = Wt + (size_t)n * KP + k;
        p[0]    = hi;
        p[1024] = hi;
        p[2048] = lo;
    }
}

// ---------------------------------------------------------------------------
// HMMA GEMM mainloop (unchanged, validated R13/R14)
// ---------------------------------------------------------------------------
#define BKC        32
#define NKCHUNK    (KP / BKC)           // 96
#define ROW_PAD    40
#define STAGE_B    (128 * ROW_PAD * 2)

struct GemmCtx {
    float acc[2][8][4];
    int gr, gc;
};

__device__ __forceinline__ void hmma_mainloop(
    const __nv_bfloat16* __restrict__ A,
    const __nv_bfloat16* __restrict__ Bt,
    __nv_bfloat16 (*As)[128][ROW_PAD], __nv_bfloat16 (*Bs)[128][ROW_PAD],
    GemmCtx& ctx)
{
    const int tid  = threadIdx.x;
    const int lane = tid & 31, wid = tid >> 5;
    const int warp_m = wid & 3;
    const int warp_n = wid >> 2;
    const int m0 = blockIdx.y * 128, n0 = blockIdx.x * 128;

    const __nv_bfloat16* Ab = A  + (size_t)m0 * KP;
    const __nv_bfloat16* Bb = Bt + (size_t)n0 * KP;

    const uint32_t sbA = smem_u32(&As[0][0][0]);
    const uint32_t sbB = smem_u32(&Bs[0][0][0]);

    const uint32_t a_base = sbA
        + (uint32_t)((warp_m * 32 + (lane & 15)) * (ROW_PAD * 2))
        + (uint32_t)((lane >> 4) * 16);
    const uint32_t b_base = sbB
        + (uint32_t)((warp_n * 64 + (lane & 7) + ((lane >> 4) & 1) * 8) * (ROW_PAD * 2))
        + (uint32_t)(((lane >> 3) & 1) * 16);

    #pragma unroll
    for (int mt = 0; mt < 2; mt++)
        #pragma unroll
        for (int nt = 0; nt < 8; nt++)
            #pragma unroll
            for (int q = 0; q < 4; q++) ctx.acc[mt][nt][q] = 0.0f;

    auto load_stage = [&](int stage, int k0) {
        #pragma unroll
        for (int i = 0; i < 2; i++) {
            int chunk = tid + i * 256;
            int row = chunk >> 2;
            int c4  = chunk & 3;
            uint32_t dst = (uint32_t)(stage * STAGE_B + row * (ROW_PAD * 2) + c4 * 16);
            cp_async16(sbA + dst, Ab + (size_t)row * KP + k0 + c4 * 8);
            cp_async16(sbB + dst, Bb + (size_t)row * KP + k0 + c4 * 8);
        }
        asm volatile("cp.async.commit_group;" ::: "memory");
    };

    load_stage(0, 0);

    for (int kc = 0; kc < NKCHUNK; kc++) {
        const int cur = kc & 1;
        if (kc + 1 < NKCHUNK) {
            load_stage(cur ^ 1, (kc + 1) * BKC);
            asm volatile("cp.async.wait_group 1;" ::: "memory");
        } else {
            asm volatile("cp.async.wait_group 0;" ::: "memory");
        }
        __syncthreads();

        const uint32_t aoff = a_base + cur * STAGE_B;
        const uint32_t boff = b_base + cur * STAGE_B;
        #pragma unroll
        for (int ks = 0; ks < 2; ks++) {
            uint32_t a0[4], a1[4];
            ldmatrix_x4(a0, aoff + ks * 32);
            ldmatrix_x4(a1, aoff + 16 * (ROW_PAD * 2) + ks * 32);
            uint32_t b[4][4];
            #pragma unroll
            for (int nt2 = 0; nt2 < 4; nt2++)
                ldmatrix_x4(b[nt2], boff + nt2 * 16 * (ROW_PAD * 2) + ks * 32);
            #pragma unroll
            for (int nt = 0; nt < 8; nt++) {
                uint32_t bb0 = b[nt >> 1][(nt & 1) * 2 + 0];
                uint32_t bb1 = b[nt >> 1][(nt & 1) * 2 + 1];
                mma_bf16(ctx.acc[0][nt], a0, bb0, bb1);
                mma_bf16(ctx.acc[1][nt], a1, bb0, bb1);
            }
        }
        __syncthreads();
    }

    ctx.gr = m0 + warp_m * 32 + (lane >> 2);
    ctx.gc = n0 + warp_n * 64 + (lane & 3) * 2;
}

__global__ __launch_bounds__(256) void hmma_gemm_kernel(
    const __nv_bfloat16* __restrict__ A,
    const __nv_bfloat16* __restrict__ Bt,
    const float* __restrict__ bias,
    float* __restrict__ C, int Nc)
{
    __shared__ __nv_bfloat16 As[2][128][ROW_PAD];
    __shared__ __nv_bfloat16 Bs[2][128][ROW_PAD];
    GemmCtx ctx;
    hmma_mainloop(A, Bt, As, Bs, ctx);

    #pragma unroll
    for (int mt = 0; mt < 2; mt++) {
        #pragma unroll
        for (int nt = 0; nt < 8; nt++) {
            int col = ctx.gc + nt * 8;
            float2 bv = *(const float2*)(bias + col);
            int r0 = ctx.gr + mt * 16;
            float2 o0 = { ctx.acc[mt][nt][0] + bv.x, ctx.acc[mt][nt][1] + bv.y };
            float2 o1 = { ctx.acc[mt][nt][2] + bv.x, ctx.acc[mt][nt][3] + bv.y };
            *(float2*)(C + (size_t)r0 * Nc + col)       = o0;
            *(float2*)(C + (size_t)(r0 + 8) * Nc + col) = o1;
        }
    }
}

__global__ __launch_bounds__(256) void hmma_gemm_qkv_kernel(
    const __nv_bfloat16* __restrict__ A,
    const __nv_bfloat16* __restrict__ Bt,
    const float* __restrict__ bias,
    __nv_bfloat16* __restrict__ q2, __nv_bfloat16* __restrict__ k2,
    __nv_bfloat16* __restrict__ vhi, __nv_bfloat16* __restrict__ vlo)
{
    __shared__ __nv_bfloat16 As[2][128][ROW_PAD];
    __shared__ __nv_bfloat16 Bs[2][128][ROW_PAD];
    GemmCtx ctx;
    hmma_mainloop(A, Bt, As, Bs, ctx);

    #pragma unroll
    for (int mt = 0; mt < 2; mt++) {
        #pragma unroll
        for (int rr = 0; rr < 2; rr++) {
            int r  = ctx.gr + mt * 16 + rr * 8;
            int bb = r >> 11, ss = r & 2047;
            #pragma unroll
            for (int nt = 0; nt < 8; nt++) {
                int col = ctx.gc + nt * 8;
                float2 bv = *(const float2*)(bias + col);
                float x = ctx.acc[mt][nt][rr * 2 + 0] + bv.x;
                float y = ctx.acc[mt][nt][rr * 2 + 1] + bv.y;
                __nv_bfloat162 hh, ll;
                split2(x, y, hh, ll);
                int sec = col >> 10;
                int h = (col & 1023) >> 6, d = col & 63;
                if (sec < 2) {
                    size_t base = ((size_t)(bb * NH + h) * S_LEN + ss) * 192 + d;
                    if (sec == 0) {            // Q: [hi | lo | hi]
                        *(__nv_bfloat162*)(q2 + base)       = hh;
                        *(__nv_bfloat162*)(q2 + base + 64)  = ll;
                        *(__nv_bfloat162*)(q2 + base + 128) = hh;
                    } else {                   // K: [hi | hi | lo]
                        *(__nv_bfloat162*)(k2 + base)       = hh;
                        *(__nv_bfloat162*)(k2 + base + 64)  = hh;
                        *(__nv_bfloat162*)(k2 + base + 128) = ll;
                    }
                } else {                       // V planes
                    size_t vb = ((size_t)(bb * NH + h) * S_LEN + ss) * 64 + d;
                    *(__nv_bfloat162*)(vhi + vb) = hh;
                    *(__nv_bfloat162*)(vlo + vb) = ll;
                }
            }
        }
    }
}

// ---------------------------------------------------------------------------
// Flash attention v3: FA2-style register-resident softmax + fragments.
// CTA = (128 queries, head, batch), 256 threads (8 warps, 16 q-rows each).
// K tile = 64 keys, double-buffered. V stored as hi/lo planes (no replication).
// 3-term splits: QK: hQ·hK + lQ·hK + hQ·lK (K'=192); PV: hP·Vhi + lP·Vhi + hP·Vlo.
// ---------------------------------------------------------------------------
#define AT_QSTR 200                       // Q/K smem row stride (elements)
#define AT_VSTR 72                        // V smem row stride (elements)
#define K_STG   (64 * AT_QSTR * 2)        // 25600 B per K stage
#define V_STG   (128 * AT_VSTR * 2)       // 18432 B per V stage (hi rows 0-63, lo 64-127)
#define AOFF_Q  0
#define AOFF_K  (128 * AT_QSTR * 2)       // 51200
#define AOFF_V  (AOFF_K + 2 * K_STG)      // 102400
#define AOFF_B  (AOFF_V + 2 * V_STG)      // 139264
#define ATTN3_SMEM_BYTES (AOFF_B + 2 * 256 * 4)   // 141312

__global__ __launch_bounds__(256) void attn_mma_kernel(
    const float* __restrict__ rel_bias, __nv_bfloat16* __restrict__ attn2)
{
    extern __shared__ char smraw[];
    const uint32_t sQ = smem_u32(smraw + AOFF_Q);
    const uint32_t sK = smem_u32(smraw + AOFF_K);
    const uint32_t sV = smem_u32(smraw + AOFF_V);
    float* bias_s = (float*)(smraw + AOFF_B);

    const int tid  = threadIdx.x;
    const int lane = tid & 31, w = tid >> 5;

    const int q0 = blockIdx.x * 128;
    const int h  = blockIdx.y;
    const int b  = blockIdx.z;
    const int bh = b * NH + h;
    const int t0 = b * S_LEN + q0;

    const __nv_bfloat16* qg = g_q2  + ((size_t)bh * S_LEN + q0) * 192;
    const __nv_bfloat16* kg = g_k2  + (size_t)bh * S_LEN * 192;
    const __nv_bfloat16* vh = g_vhi + (size_t)bh * S_LEN * 64;
    const __nv_bfloat16* vl = g_vlo + (size_t)bh * S_LEN * 64;

    auto load_tile = [&](int stg, int j0) {
        // K' tile: 64 rows x 192 elems = 24 16B-chunks/row
        #pragma unroll
        for (int it = 0; it < 6; it++) {
            int c = tid + it * 256;
            int row = c / 24, u = c % 24;
            cp_async16(sK + (uint32_t)(stg * K_STG + row * (AT_QSTR * 2) + u * 16),
                       kg + (size_t)(j0 + row) * 192 + u * 8);
        }
        // V: hi rows 0-63, lo rows 64-127; 8 chunks/row
        #pragma unroll
        for (int it = 0; it < 4; it++) {
            int c = tid + it * 256;
            int row = c >> 3, u = c & 7;
            const __nv_bfloat16* src = (row < 64)
                ? vh + (size_t)(j0 + row) * 64 + u * 8
                : vl + (size_t)(j0 + row - 64) * 64 + u * 8;
            cp_async16(sV + (uint32_t)(stg * V_STG + row * (AT_VSTR * 2) + u * 16), src);
        }
        if (tid < 191) {
            int rel = (q0 - j0) + (tid - 63) + 1024;
            rel = min(max(rel, 0), 2 * 1024);
            bias_s[stg * 256 + tid] = __ldg(rel_bias + rel * NH + h);
        }
        asm volatile("cp.async.commit_group;" ::: "memory");
    };

    // Q tile (joins group 0 with tile 0)
    #pragma unroll
    for (int it = 0; it < 12; it++) {
        int c = tid + it * 256;
        int row = c / 24, u = c % 24;
        cp_async16(sQ + (uint32_t)(row * (AT_QSTR * 2) + u * 16),
                   qg + (size_t)row * 192 + u * 8);
    }
    load_tile(0, 0);

    const uint32_t aQ = sQ + (uint32_t)((w * 16 + (lane & 15)) * (AT_QSTR * 2)
                                        + (lane >> 4) * 16);
    const uint32_t bK = sK + (uint32_t)((((lane & 7) + ((lane >> 4) & 1) * 8) * (AT_QSTR * 2))
                                        + ((lane >> 3) & 1) * 16);
    const uint32_t bV = sV + (uint32_t)((lane & 15) * (AT_VSTR * 2) + (lane >> 4) * 16);

    float o[8][4];
    #pragma unroll
    for (int nt = 0; nt < 8; nt++)
        #pragma unroll
        for (int q = 0; q < 4; q++) o[nt][q] = 0.0f;

    float mA = -1e30f, mB = -1e30f, lA = 0.0f, lB = 0.0f;
    const int r0  = lane >> 2;
    const int c0q = (lane & 3) * 2;
    const int rA  = w * 16 + r0, rB = rA + 8;   // rows within the 128-q tile

    for (int j = 0; j < S_LEN / 64; j++) {
        const int s = j & 1;
        if (j + 1 < S_LEN / 64) {
            load_tile(s ^ 1, (j + 1) * 64);
            asm volatile("cp.async.wait_group 1;" ::: "memory");
        } else {
            asm volatile("cp.async.wait_group 0;" ::: "memory");
        }
        __syncthreads();

        const uint32_t kb = bK + s * K_STG;
        const uint32_t vb = bV + s * V_STG;
        const float* bs = bias_s + s * 256;

        // --- S = Q' @ K'^T over k'=192 ---
        float sf[8][4];
        #pragma unroll
        for (int nt = 0; nt < 8; nt++)
            #pragma unroll
            for (int q = 0; q < 4; q++) sf[nt][q] = 0.0f;
        #pragma unroll
        for (int kt = 0; kt < 12; kt++) {
            uint32_t a[4];
            ldmatrix_x4(a, aQ + kt * 32);
            #pragma unroll
            for (int np = 0; np < 4; np++) {
                uint32_t bf[4];
                ldmatrix_x4(bf, kb + np * 16 * (AT_QSTR * 2) + kt * 32);
                mma_bf16(sf[np * 2 + 0], a, bf[0], bf[1]);
                mma_bf16(sf[np * 2 + 1], a, bf[2], bf[3]);
            }
        }

        // --- scale + rel-bias, register-resident online softmax ---
        float mlA = -1e30f, mlB = -1e30f;
        #pragma unroll
        for (int nt = 0; nt < 8; nt++) {
            int c = nt * 8 + c0q;
            sf[nt][0] = fmaf(sf[nt][0], 0.125f, bs[rA - c + 63]);
            sf[nt][1] = fmaf(sf[nt][1], 0.125f, bs[rA - c + 62]);
            sf[nt][2] = fmaf(sf[nt][2], 0.125f, bs[rB - c + 63]);
            sf[nt][3] = fmaf(sf[nt][3], 0.125f, bs[rB - c + 62]);
            mlA = fmaxf(mlA, fmaxf(sf[nt][0], sf[nt][1]));
            mlB = fmaxf(mlB, fmaxf(sf[nt][2], sf[nt][3]));
        }
        mlA = fmaxf(mlA, __shfl_xor_sync(0xffffffffu, mlA, 1));
        mlA = fmaxf(mlA, __shfl_xor_sync(0xffffffffu, mlA, 2));
        mlB = fmaxf(mlB, __shfl_xor_sync(0xffffffffu, mlB, 1));
        mlB = fmaxf(mlB, __shfl_xor_sync(0xffffffffu, mlB, 2));

        float mnA = fmaxf(mA, mlA), mnB = fmaxf(mB, mlB);
        float escA = __expf(mA - mnA), escB = __expf(mB - mnB);
        float rsA = 0.0f, rsB = 0.0f;
        #pragma unroll
        for (int nt = 0; nt < 8; nt++) {
            sf[nt][0] = __expf(sf[nt][0] - mnA);
            sf[nt][1] = __expf(sf[nt][1] - mnA);
            sf[nt][2] = __expf(sf[nt][2] - mnB);
            sf[nt][3] = __expf(sf[nt][3] - mnB);
            rsA += sf[nt][0] + sf[nt][1];
            rsB += sf[nt][2] + sf[nt][3];
        }
        rsA += __shfl_xor_sync(0xffffffffu, rsA, 1);
        rsA += __shfl_xor_sync(0xffffffffu, rsA, 2);
        rsB += __shfl_xor_sync(0xffffffffu, rsB, 1);
        rsB += __shfl_xor_sync(0xffffffffu, rsB, 2);
        lA = lA * escA + rsA; mA = mnA;
        lB = lB * escB + rsB; mB = mnB;

        #pragma unroll
        for (int nt = 0; nt < 8; nt++) {
            o[nt][0] *= escA; o[nt][1] *= escA;
            o[nt][2] *= escB; o[nt][3] *= escB;
        }

        // --- O += hP·Vhi + lP·Vhi + hP·Vlo (P frags built in registers) ---
        #pragma unroll
        for (int kt = 0; kt < 4; kt++) {
            uint32_t aH[4], aL[4];
            pack_hilo(sf[2 * kt][0],     sf[2 * kt][1],     aH[0], aL[0]);
            pack_hilo(sf[2 * kt][2],     sf[2 * kt][3],     aH[1], aL[1]);
            pack_hilo(sf[2 * kt + 1][0], sf[2 * kt + 1][1], aH[2], aL[2]);
            pack_hilo(sf[2 * kt + 1][2], sf[2 * kt + 1][3], aH[3], aL[3]);
            #pragma unroll
            for (int np = 0; np < 4; np++) {
                uint32_t bh_[4], bl_[4];
                ldmatrix_x4_trans(bh_, vb + kt * 16 * (AT_VSTR * 2) + np * 32);
                ldmatrix_x4_trans(bl_, vb + (64 + kt * 16) * (AT_VSTR * 2) + np * 32);
                mma_bf16(o[np * 2 + 0], aH, bh_[0], bh_[1]);
                mma_bf16(o[np * 2 + 1], aH, bh_[2], bh_[3]);
                mma_bf16(o[np * 2 + 0], aL, bh_[0], bh_[1]);
                mma_bf16(o[np * 2 + 1], aL, bh_[2], bh_[3]);
                mma_bf16(o[np * 2 + 0], aH, bl_[0], bl_[1]);
                mma_bf16(o[np * 2 + 1], aH, bl_[2], bl_[3]);
            }
        }
        __syncthreads();   // stage-s reads done before iter j+1 overwrites it
    }

    // --- epilogue: normalize, split, write g_attn2[token][hi|lo|hi] ---
    {
        const float iA = 1.0f / lA, iB = 1.0f / lB;
        const int tokA = t0 + rA, tokB = t0 + rB;
        const int colb = h * DK + c0q;
        #pragma unroll
        for (int nt = 0; nt < 8; nt++) {
            int col = colb + nt * 8;
            {
                float x = o[nt][0] * iA, y = o[nt][1] * iA;
                __nv_bfloat162 hh, ll;
                split2(x, y, hh, ll);
                __nv_bfloat16* p = attn2 + (size_t)tokA * KP + col;
                *(__nv_bfloat162*)(p)        = hh;
                *(__nv_bfloat162*)(p + 1024) = ll;
                *(__nv_bfloat162*)(p + 2048) = hh;
            }
            {
                float x = o[nt][2] * iB, y = o[nt][3] * iB;
                __nv_bfloat162 hh, ll;
                split2(x, y, hh, ll);
                __nv_bfloat16* p = attn2 + (size_t)tokB * KP + col;
                *(__nv_bfloat162*)(p)        = hh;
                *(__nv_bfloat162*)(p + 1024) = ll;
                *(__nv_bfloat162*)(p + 2048) = hh;
            }
        }
    }
}

// ---------------------------------------------------------------------------
// Launch
// ---------------------------------------------------------------------------
extern "C" void kernel_launch(void* const* d_in, const int* in_sizes, int n_in,
                              void* d_out, int out_size)
{
    const float* x        = (const float*)d_in[0];
    const float* W_qkv    = (const float*)d_in[1];
    const float* b_qkv    = (const float*)d_in[2];
    const float* W_out    = (const float*)d_in[3];
    const float* b_out    = (const float*)d_in[4];
    const float* rel_bias = (const float*)d_in[5];
    float* out = (float*)d_out;

    __nv_bfloat16 *x2p, *a2p, *wqp, *wop, *q2p, *k2p, *vhp, *vlp;
    cudaGetSymbolAddress((void**)&x2p, g_x2);
    cudaGetSymbolAddress((void**)&a2p, g_attn2);
    cudaGetSymbolAddress((void**)&wqp, g_w2qkv);
    cudaGetSymbolAddress((void**)&wop, g_w2out);
    cudaGetSymbolAddress((void**)&q2p, g_q2);
    cudaGetSymbolAddress((void**)&k2p, g_k2);
    cudaGetSymbolAddress((void**)&vhp, g_vhi);
    cudaGetSymbolAddress((void**)&vlp, g_vlo);

    cudaFuncSetAttribute(attn_mma_kernel,
                         cudaFuncAttributeMaxDynamicSharedMemorySize,
                         ATTN3_SMEM_BYTES);

    // 0) Conversions
    convert_x_kernel<<<TOK * DM / 512, 256>>>(x, x2p);
    {
        dim3 wb(32, 8);
        convert_w_kernel<<<dim3(QKV_N / 32, DM / 32), wb>>>(W_qkv, wqp, QKV_N);
        convert_w_kernel<<<dim3(DM / 32, DM / 32),   wb>>>(W_out, wop, DM);
    }

    // 1) QKV projection -> pre-split attention operands
    {
        dim3 grid(QKV_N / 128, TOK / 128);
        hmma_gemm_qkv_kernel<<<grid, 256>>>(x2p, wqp, b_qkv,
                                            q2p, k2p, vhp, vlp);
    }
    // 2) Attention (FA2-style HMMA, register softmax), writes split bf16
    {
        dim3 grid(S_LEN / 128, NH, 4);
        attn_mma_kernel<<<grid, 256, ATTN3_SMEM_BYTES>>>(rel_bias, a2p);
    }
    // 3) Output projection -> d_out
    {
        dim3 grid(DM / 128, TOK / 128);
        hmma_gemm_kernel<<<grid, 256>>>(a2p, wop, b_out, out, DM);
    }
}

// round 16
// speedup vs baseline: 4.6749x; 1.6779x over previous
#include <cuda_runtime.h>
#include <cuda_fp16.h>
#include <math.h>
#include <stdint.h>

#define TOK    8192      // B*S
#define DM     1024
#define S_LEN  2048
#define NH     16
#define DK     64
#define QKV_N  3072
#define KP     2048      // K' = 2*1024 (fp16 hi/lo split folded into K)

// ---------------------------------------------------------------------------
// Static device scratch
// ---------------------------------------------------------------------------
__device__ __half g_x2   [(size_t)TOK   * KP];   // x split: [hi | lo]
__device__ __half g_attn2[(size_t)TOK   * KP];   // attn out split: [hi | lo]
__device__ __half g_w2qkv[(size_t)QKV_N * KP];   // W_qkv^T: [hi | hi]
__device__ __half g_w2out[(size_t)DM    * KP];   // W_out^T: [hi | hi]
// attention operands, per (b,h) contiguous:
__device__ __half g_q2 [(size_t)4 * NH * S_LEN * 128];  // [bh][s][hi(64)|lo(64)]
__device__ __half g_khi[(size_t)4 * NH * S_LEN * 64];   // K hi plane only
__device__ __half g_vhi[(size_t)4 * NH * S_LEN * 64];   // V hi plane only

// ---------------------------------------------------------------------------
// PTX helpers (baseline ISA: ldmatrix / mma.sync / cp.async — valid on sm_103)
// ---------------------------------------------------------------------------
__device__ __forceinline__ uint32_t smem_u32(const void* p) {
    uint32_t a;
    asm("{ .reg .u64 t; cvta.to.shared.u64 t, %1; cvt.u32.u64 %0, t; }"
        : "=r"(a) : "l"(p));
    return a;
}

__device__ __forceinline__ void cp_async16(uint32_t saddr, const void* gaddr) {
    asm volatile("cp.async.cg.shared.global [%0], [%1], 16;"
                 :: "r"(saddr), "l"(gaddr) : "memory");
}

__device__ __forceinline__ void ldmatrix_x4(uint32_t* r, uint32_t addr) {
    asm volatile("ldmatrix.sync.aligned.m8n8.x4.shared.b16 {%0,%1,%2,%3}, [%4];"
                 : "=r"(r[0]), "=r"(r[1]), "=r"(r[2]), "=r"(r[3]) : "r"(addr));
}

__device__ __forceinline__ void ldmatrix_x4_trans(uint32_t* r, uint32_t addr) {
    asm volatile("ldmatrix.sync.aligned.m8n8.x4.trans.shared.b16 {%0,%1,%2,%3}, [%4];"
                 : "=r"(r[0]), "=r"(r[1]), "=r"(r[2]), "=r"(r[3]) : "r"(addr));
}

__device__ __forceinline__ void mma_f16(float* c, const uint32_t* a,
                                        uint32_t b0, uint32_t b1) {
    asm volatile(
        "mma.sync.aligned.m16n8k16.row.col.f32.f16.f16.f32 "
        "{%0,%1,%2,%3}, {%4,%5,%6,%7}, {%8,%9}, {%0,%1,%2,%3};"
        : "+f"(c[0]), "+f"(c[1]), "+f"(c[2]), "+f"(c[3])
        : "r"(a[0]), "r"(a[1]), "r"(a[2]), "r"(a[3]), "r"(b0), "r"(b1));
}

__device__ __forceinline__ void split2h(float x, float y,
                                        __half2& hh, __half2& ll) {
    __half h0 = __float2half_rn(x);
    __half h1 = __float2half_rn(y);
    __half l0 = __float2half_rn(x - __half2float(h0));
    __half l1 = __float2half_rn(y - __half2float(h1));
    hh = __halves2half2(h0, h1);
    ll = __halves2half2(l0, l1);
}

__device__ __forceinline__ void pack_hilo(float x, float y,
                                          uint32_t& hh, uint32_t& ll) {
    __half2 H, L;
    split2h(x, y, H, L);
    hh = *reinterpret_cast<uint32_t*>(&H);
    ll = *reinterpret_cast<uint32_t*>(&L);
}

// ---------------------------------------------------------------------------
// Conversion kernels: fp32 -> fp16 hi/lo split
// x2[row]: [hi(0:1024) | lo(1024:2048)];  Wt[n]: [hi | hi]
// => A'·B' = hiA·hiB + loA·hiB  (drops A·loB ~ 2^-12 rel)
// ---------------------------------------------------------------------------
__global__ __launch_bounds__(256) void convert_x_kernel(
    const float* __restrict__ x, __half* __restrict__ x2)
{
    size_t i = (size_t)blockIdx.x * 256 + threadIdx.x;
    size_t e = i * 2;
    size_t row = e >> 10;
    int col = (int)(e & 1023);
    float2 v = *(const float2*)(x + row * DM + col);
    __half2 hh, ll;
    split2h(v.x, v.y, hh, ll);
    __half* base = x2 + row * KP + col;
    *(__half2*)(base)        = hh;
    *(__half2*)(base + 1024) = ll;
}

__global__ __launch_bounds__(256) void convert_w_kernel(
    const float* __restrict__ W,       // [1024][N] row-major
    __half* __restrict__ Wt,           // [N][KP]
    int N)
{
    __shared__ float tile[32][33];
    const int n0 = blockIdx.x * 32, k0 = blockIdx.y * 32;
    const int tx = threadIdx.x, ty = threadIdx.y;
    #pragma unroll
    for (int r = ty; r < 32; r += 8)
        tile[r][tx] = W[(size_t)(k0 + r) * N + n0 + tx];
    __syncthreads();
    #pragma unroll
    for (int r = ty; r < 32; r += 8) {
        int n = n0 + r, k = k0 + tx;
        __half hi = __float2half_rn(tile[tx][r]);
        __half* p = Wt + (size_t)n * KP + k;
        p[0]    = hi;
        p[1024] = hi;
    }
}

// ---------------------------------------------------------------------------
// HMMA GEMM mainloop: 128x128 tile, BK=32, 256 threads (8 warps 4x2),
// m16n8k16, 2-stage cp.async with single sync per chunk.
// ---------------------------------------------------------------------------
#define BKC        32
#define NKCHUNK    (KP / BKC)           // 64
#define ROW_PAD    40
#define STAGE_B    (128 * ROW_PAD * 2)

struct GemmCtx {
    float acc[2][8][4];
    int gr, gc;
};

__device__ __forceinline__ void hmma_mainloop(
    const __half* __restrict__ A,
    const __half* __restrict__ Bt,
    __half (*As)[128][ROW_PAD], __half (*Bs)[128][ROW_PAD],
    GemmCtx& ctx)
{
    const int tid  = threadIdx.x;
    const int lane = tid & 31, wid = tid >> 5;
    const int warp_m = wid & 3;
    const int warp_n = wid >> 2;
    const int m0 = blockIdx.y * 128, n0 = blockIdx.x * 128;

    const __half* Ab = A  + (size_t)m0 * KP;
    const __half* Bb = Bt + (size_t)n0 * KP;

    const uint32_t sbA = smem_u32(&As[0][0][0]);
    const uint32_t sbB = smem_u32(&Bs[0][0][0]);

    const uint32_t a_base = sbA
        + (uint32_t)((warp_m * 32 + (lane & 15)) * (ROW_PAD * 2))
        + (uint32_t)((lane >> 4) * 16);
    const uint32_t b_base = sbB
        + (uint32_t)((warp_n * 64 + (lane & 7) + ((lane >> 4) & 1) * 8) * (ROW_PAD * 2))
        + (uint32_t)(((lane >> 3) & 1) * 16);

    #pragma unroll
    for (int mt = 0; mt < 2; mt++)
        #pragma unroll
        for (int nt = 0; nt < 8; nt++)
            #pragma unroll
            for (int q = 0; q < 4; q++) ctx.acc[mt][nt][q] = 0.0f;

    auto load_stage = [&](int stage, int k0) {
        #pragma unroll
        for (int i = 0; i < 2; i++) {
            int chunk = tid + i * 256;
            int row = chunk >> 2;
            int c4  = chunk & 3;
            uint32_t dst = (uint32_t)(stage * STAGE_B + row * (ROW_PAD * 2) + c4 * 16);
            cp_async16(sbA + dst, Ab + (size_t)row * KP + k0 + c4 * 8);
            cp_async16(sbB + dst, Bb + (size_t)row * KP + k0 + c4 * 8);
        }
        asm volatile("cp.async.commit_group;" ::: "memory");
    };

    load_stage(0, 0);

    for (int kc = 0; kc < NKCHUNK; kc++) {
        const int cur = kc & 1;
        asm volatile("cp.async.wait_group 0;" ::: "memory");
        __syncthreads();
        if (kc + 1 < NKCHUNK) load_stage(cur ^ 1, (kc + 1) * BKC);

        const uint32_t aoff = a_base + cur * STAGE_B;
        const uint32_t boff = b_base + cur * STAGE_B;
        #pragma unroll
        for (int ks = 0; ks < 2; ks++) {
            uint32_t a0[4], a1[4];
            ldmatrix_x4(a0, aoff + ks * 32);
            ldmatrix_x4(a1, aoff + 16 * (ROW_PAD * 2) + ks * 32);
            uint32_t b[4][4];
            #pragma unroll
            for (int nt2 = 0; nt2 < 4; nt2++)
                ldmatrix_x4(b[nt2], boff + nt2 * 16 * (ROW_PAD * 2) + ks * 32);
            #pragma unroll
            for (int nt = 0; nt < 8; nt++) {
                uint32_t bb0 = b[nt >> 1][(nt & 1) * 2 + 0];
                uint32_t bb1 = b[nt >> 1][(nt & 1) * 2 + 1];
                mma_f16(ctx.acc[0][nt], a0, bb0, bb1);
                mma_f16(ctx.acc[1][nt], a1, bb0, bb1);
            }
        }
    }

    ctx.gr = m0 + warp_m * 32 + (lane >> 2);
    ctx.gc = n0 + warp_n * 64 + (lane & 3) * 2;
}

__global__ __launch_bounds__(256) void hmma_gemm_kernel(
    const __half* __restrict__ A,
    const __half* __restrict__ Bt,
    const float* __restrict__ bias,
    float* __restrict__ C, int Nc)
{
    __shared__ __half As[2][128][ROW_PAD];
    __shared__ __half Bs[2][128][ROW_PAD];
    GemmCtx ctx;
    hmma_mainloop(A, Bt, As, Bs, ctx);

    #pragma unroll
    for (int mt = 0; mt < 2; mt++) {
        #pragma unroll
        for (int nt = 0; nt < 8; nt++) {
            int col = ctx.gc + nt * 8;
            float2 bv = *(const float2*)(bias + col);
            int r0 = ctx.gr + mt * 16;
            float2 o0 = { ctx.acc[mt][nt][0] + bv.x, ctx.acc[mt][nt][1] + bv.y };
            float2 o1 = { ctx.acc[mt][nt][2] + bv.x, ctx.acc[mt][nt][3] + bv.y };
            *(float2*)(C + (size_t)r0 * Nc + col)       = o0;
            *(float2*)(C + (size_t)(r0 + 8) * Nc + col) = o1;
        }
    }
}

// QKV variant: writes pre-split attention operands q2/khi/vhi
__global__ __launch_bounds__(256) void hmma_gemm_qkv_kernel(
    const __half* __restrict__ A,
    const __half* __restrict__ Bt,
    const float* __restrict__ bias,
    __half* __restrict__ q2, __half* __restrict__ khi,
    __half* __restrict__ vhi)
{
    __shared__ __half As[2][128][ROW_PAD];
    __shared__ __half Bs[2][128][ROW_PAD];
    GemmCtx ctx;
    hmma_mainloop(A, Bt, As, Bs, ctx);

    #pragma unroll
    for (int mt = 0; mt < 2; mt++) {
        #pragma unroll
        for (int rr = 0; rr < 2; rr++) {
            int r  = ctx.gr + mt * 16 + rr * 8;
            int bb = r >> 11, ss = r & 2047;
            #pragma unroll
            for (int nt = 0; nt < 8; nt++) {
                int col = ctx.gc + nt * 8;
                float2 bv = *(const float2*)(bias + col);
                float x = ctx.acc[mt][nt][rr * 2 + 0] + bv.x;
                float y = ctx.acc[mt][nt][rr * 2 + 1] + bv.y;
                __half2 hh, ll;
                split2h(x, y, hh, ll);
                int sec = col >> 10;
                int h = (col & 1023) >> 6, d = col & 63;
                if (sec == 0) {                 // Q: [hi | lo]
                    size_t base = ((size_t)(bb * NH + h) * S_LEN + ss) * 128 + d;
                    *(__half2*)(q2 + base)      = hh;
                    *(__half2*)(q2 + base + 64) = ll;
                } else {
                    size_t base = ((size_t)(bb * NH + h) * S_LEN + ss) * 64 + d;
                    if (sec == 1) *(__half2*)(khi + base) = hh;
                    else          *(__half2*)(vhi + base) = hh;
                }
            }
        }
    }
}

// ---------------------------------------------------------------------------
// Flash attention: FA2-style register softmax, fp16 2-term splits.
// CTA = (128 queries, head, batch), 256 threads (8 warps, 16 q-rows each).
// QK: (hQ + lQ)·hK over d=64 (B-frag reused for both A terms).
// PV: (hP + lP)·hV.
// Smem: Q[128][136] | K 2x[64][72] | V 2x[64][72] | bias 2x256 f32
// ---------------------------------------------------------------------------
#define AQ_STR 136                         // Q row stride (halves), 272 B
#define KV_STR 72                          // K/V row stride (halves), 144 B
#define K_STG  (64 * KV_STR * 2)           // 9216 B
#define AOFF_Q 0
#define AOFF_K (128 * AQ_STR * 2)          // 34816
#define AOFF_V (AOFF_K + 2 * K_STG)        // 53248
#define AOFF_B (AOFF_V + 2 * K_STG)        // 71680
#define ATTN_SMEM_BYTES (AOFF_B + 2 * 256 * 4)   // 73728

__global__ __launch_bounds__(256) void attn_mma_kernel(
    const float* __restrict__ rel_bias, __half* __restrict__ attn2)
{
    extern __shared__ char smraw[];
    const uint32_t sQ = smem_u32(smraw + AOFF_Q);
    const uint32_t sK = smem_u32(smraw + AOFF_K);
    const uint32_t sV = smem_u32(smraw + AOFF_V);
    float* bias_s = (float*)(smraw + AOFF_B);

    const int tid  = threadIdx.x;
    const int lane = tid & 31, w = tid >> 5;

    const int q0 = blockIdx.x * 128;
    const int h  = blockIdx.y;
    const int b  = blockIdx.z;
    const int bh = b * NH + h;
    const int t0 = b * S_LEN + q0;

    const __half* qg = g_q2  + ((size_t)bh * S_LEN + q0) * 128;
    const __half* kg = g_khi + (size_t)bh * S_LEN * 64;
    const __half* vg = g_vhi + (size_t)bh * S_LEN * 64;

    auto load_tile = [&](int stg, int j0) {
        // K hi: 64 rows x 64 halves = 8 chunks/row -> 512 chunks, 2/thread
        #pragma unroll
        for (int it = 0; it < 2; it++) {
            int c = tid + it * 256;
            int row = c >> 3, u = c & 7;
            cp_async16(sK + (uint32_t)(stg * K_STG + row * (KV_STR * 2) + u * 16),
                       kg + (size_t)(j0 + row) * 64 + u * 8);
        }
        #pragma unroll
        for (int it = 0; it < 2; it++) {
            int c = tid + it * 256;
            int row = c >> 3, u = c & 7;
            cp_async16(sV + (uint32_t)(stg * K_STG + row * (KV_STR * 2) + u * 16),
                       vg + (size_t)(j0 + row) * 64 + u * 8);
        }
        if (tid < 191) {
            int rel = (q0 - j0) + (tid - 63) + 1024;
            rel = min(max(rel, 0), 2 * 1024);
            bias_s[stg * 256 + tid] = __ldg(rel_bias + rel * NH + h);
        }
        asm volatile("cp.async.commit_group;" ::: "memory");
    };

    // Q tile: 128 rows x 128 halves = 16 chunks/row -> 2048 chunks, 8/thread
    #pragma unroll
    for (int it = 0; it < 8; it++) {
        int c = tid + it * 256;
        int row = c >> 4, u = c & 15;
        cp_async16(sQ + (uint32_t)(row * (AQ_STR * 2) + u * 16),
                   qg + (size_t)row * 128 + u * 8);
    }
    load_tile(0, 0);

    const uint32_t aQ = sQ + (uint32_t)((w * 16 + (lane & 15)) * (AQ_STR * 2)
                                        + (lane >> 4) * 16);
    const uint32_t bK = sK + (uint32_t)((((lane & 7) + ((lane >> 4) & 1) * 8) * (KV_STR * 2))
                                        + ((lane >> 3) & 1) * 16);
    const uint32_t bV = sV + (uint32_t)((lane & 15) * (KV_STR * 2) + (lane >> 4) * 16);

    float o[8][4];
    #pragma unroll
    for (int nt = 0; nt < 8; nt++)
        #pragma unroll
        for (int q = 0; q < 4; q++) o[nt][q] = 0.0f;

    float mA = -1e30f, mB = -1e30f, lA = 0.0f, lB = 0.0f;
    const int r0  = lane >> 2;
    const int c0q = (lane & 3) * 2;
    const int rA  = w * 16 + r0, rB = rA + 8;

    for (int j = 0; j < S_LEN / 64; j++) {
        const int s = j & 1;
        asm volatile("cp.async.wait_group 0;" ::: "memory");
        __syncthreads();
        if (j + 1 < S_LEN / 64) load_tile(s ^ 1, (j + 1) * 64);

        const uint32_t kb = bK + s * K_STG;
        const uint32_t vb = bV + s * K_STG;
        const float* bs = bias_s + s * 256;

        // --- S = (hQ + lQ) @ hK^T over d=64 ---
        float sf[8][4];
        #pragma unroll
        for (int nt = 0; nt < 8; nt++)
            #pragma unroll
            for (int q = 0; q < 4; q++) sf[nt][q] = 0.0f;
        #pragma unroll
        for (int kt = 0; kt < 4; kt++) {
            uint32_t aH[4], aL[4];
            ldmatrix_x4(aH, aQ + kt * 32);          // hi section, bytes 0..127
            ldmatrix_x4(aL, aQ + 128 + kt * 32);    // lo section, bytes 128..255
            #pragma unroll
            for (int np = 0; np < 4; np++) {
                uint32_t bf[4];
                ldmatrix_x4(bf, kb + np * 16 * (KV_STR * 2) + kt * 32);
                mma_f16(sf[np * 2 + 0], aH, bf[0], bf[1]);
                mma_f16(sf[np * 2 + 1], aH, bf[2], bf[3]);
                mma_f16(sf[np * 2 + 0], aL, bf[0], bf[1]);
                mma_f16(sf[np * 2 + 1], aL, bf[2], bf[3]);
            }
        }

        // --- scale + rel-bias, register-resident online softmax ---
        float mlA = -1e30f, mlB = -1e30f;
        #pragma unroll
        for (int nt = 0; nt < 8; nt++) {
            int c = nt * 8 + c0q;
            sf[nt][0] = fmaf(sf[nt][0], 0.125f, bs[rA - c + 63]);
            sf[nt][1] = fmaf(sf[nt][1], 0.125f, bs[rA - c + 62]);
            sf[nt][2] = fmaf(sf[nt][2], 0.125f, bs[rB - c + 63]);
            sf[nt][3] = fmaf(sf[nt][3], 0.125f, bs[rB - c + 62]);
            mlA = fmaxf(mlA, fmaxf(sf[nt][0], sf[nt][1]));
            mlB = fmaxf(mlB, fmaxf(sf[nt][2], sf[nt][3]));
        }
        mlA = fmaxf(mlA, __shfl_xor_sync(0xffffffffu, mlA, 1));
        mlA = fmaxf(mlA, __shfl_xor_sync(0xffffffffu, mlA, 2));
        mlB = fmaxf(mlB, __shfl_xor_sync(0xffffffffu, mlB, 1));
        mlB = fmaxf(mlB, __shfl_xor_sync(0xffffffffu, mlB, 2));

        float mnA = fmaxf(mA, mlA), mnB = fmaxf(mB, mlB);
        float escA = __expf(mA - mnA), escB = __expf(mB - mnB);
        float rsA = 0.0f, rsB = 0.0f;
        #pragma unroll
        for (int nt = 0; nt < 8; nt++) {
            sf[nt][0] = __expf(sf[nt][0] - mnA);
            sf[nt][1] = __expf(sf[nt][1] - mnA);
            sf[nt][2] = __expf(sf[nt][2] - mnB);
            sf[nt][3] = __expf(sf[nt][3] - mnB);
            rsA += sf[nt][0] + sf[nt][1];
            rsB += sf[nt][2] + sf[nt][3];
        }
        rsA += __shfl_xor_sync(0xffffffffu, rsA, 1);
        rsA += __shfl_xor_sync(0xffffffffu, rsA, 2);
        rsB += __shfl_xor_sync(0xffffffffu, rsB, 1);
        rsB += __shfl_xor_sync(0xffffffffu, rsB, 2);
        lA = lA * escA + rsA; mA = mnA;
        lB = lB * escB + rsB; mB = mnB;

        #pragma unroll
        for (int nt = 0; nt < 8; nt++) {
            o[nt][0] *= escA; o[nt][1] *= escA;
            o[nt][2] *= escB; o[nt][3] *= escB;
        }

        // --- O += (hP + lP) @ hV (P frags built in registers) ---
        #pragma unroll
        for (int kt = 0; kt < 4; kt++) {
            uint32_t aH[4], aL[4];
            pack_hilo(sf[2 * kt][0],     sf[2 * kt][1],     aH[0], aL[0]);
            pack_hilo(sf[2 * kt][2],     sf[2 * kt][3],     aH[1], aL[1]);
            pack_hilo(sf[2 * kt + 1][0], sf[2 * kt + 1][1], aH[2], aL[2]);
            pack_hilo(sf[2 * kt + 1][2], sf[2 * kt + 1][3], aH[3], aL[3]);
            #pragma unroll
            for (int np = 0; np < 4; np++) {
                uint32_t bf[4];
                ldmatrix_x4_trans(bf, vb + kt * 16 * (KV_STR * 2) + np * 32);
                mma_f16(o[np * 2 + 0], aH, bf[0], bf[1]);
                mma_f16(o[np * 2 + 1], aH, bf[2], bf[3]);
                mma_f16(o[np * 2 + 0], aL, bf[0], bf[1]);
                mma_f16(o[np * 2 + 1], aL, bf[2], bf[3]);
            }
        }
    }

    // --- epilogue: normalize, split, write g_attn2[token][hi|lo] ---
    {
        const float iA = 1.0f / lA, iB = 1.0f / lB;
        const int tokA = t0 + rA, tokB = t0 + rB;
        const int colb = h * DK + c0q;
        #pragma unroll
        for (int nt = 0; nt < 8; nt++) {
            int col = colb + nt * 8;
            {
                __half2 hh, ll;
                split2h(o[nt][0] * iA, o[nt][1] * iA, hh, ll);
                __half* p = attn2 + (size_t)tokA * KP + col;
                *(__half2*)(p)        = hh;
                *(__half2*)(p + 1024) = ll;
            }
            {
                __half2 hh, ll;
                split2h(o[nt][2] * iB, o[nt][3] * iB, hh, ll);
                __half* p = attn2 + (size_t)tokB * KP + col;
                *(__half2*)(p)        = hh;
                *(__half2*)(p + 1024) = ll;
            }
        }
    }
}

// ---------------------------------------------------------------------------
// Launch
// ---------------------------------------------------------------------------
extern "C" void kernel_launch(void* const* d_in, const int* in_sizes, int n_in,
                              void* d_out, int out_size)
{
    const float* x        = (const float*)d_in[0];
    const float* W_qkv    = (const float*)d_in[1];
    const float* b_qkv    = (const float*)d_in[2];
    const float* W_out    = (const float*)d_in[3];
    const float* b_out    = (const float*)d_in[4];
    const float* rel_bias = (const float*)d_in[5];
    float* out = (float*)d_out;

    __half *x2p, *a2p, *wqp, *wop, *q2p, *khp, *vhp;
    cudaGetSymbolAddress((void**)&x2p, g_x2);
    cudaGetSymbolAddress((void**)&a2p, g_attn2);
    cudaGetSymbolAddress((void**)&wqp, g_w2qkv);
    cudaGetSymbolAddress((void**)&wop, g_w2out);
    cudaGetSymbolAddress((void**)&q2p, g_q2);
    cudaGetSymbolAddress((void**)&khp, g_khi);
    cudaGetSymbolAddress((void**)&vhp, g_vhi);

    cudaFuncSetAttribute(attn_mma_kernel,
                         cudaFuncAttributeMaxDynamicSharedMemorySize,
                         ATTN_SMEM_BYTES);

    // 0) Conversions
    convert_x_kernel<<<TOK * DM / 512, 256>>>(x, x2p);
    {
        dim3 wb(32, 8);
        convert_w_kernel<<<dim3(QKV_N / 32, DM / 32), wb>>>(W_qkv, wqp, QKV_N);
        convert_w_kernel<<<dim3(DM / 32, DM / 32),   wb>>>(W_out, wop, DM);
    }

    // 1) QKV projection -> pre-split attention operands
    {
        dim3 grid(QKV_N / 128, TOK / 128);
        hmma_gemm_qkv_kernel<<<grid, 256>>>(x2p, wqp, b_qkv, q2p, khp, vhp);
    }
    // 2) Attention (FA2-style HMMA, register softmax), writes split fp16
    {
        dim3 grid(S_LEN / 128, NH, 4);
        attn_mma_kernel<<<grid, 256, ATTN_SMEM_BYTES>>>(rel_bias, a2p);
    }
    // 3) Output projection -> d_out
    {
        dim3 grid(DM / 128, TOK / 128);
        hmma_gemm_kernel<<<grid, 256>>>(a2p, wop, b_out, out, DM);
    }
}